// round 12
// baseline (speedup 1.0000x reference)
#include <cuda_runtime.h>
#include <cuda_fp16.h>
#include <float.h>

// ---------------------------------------------------------------------------
// Problem constants
// ---------------------------------------------------------------------------
#define Bn     16
#define Hn     16
#define DHn    64
#define NTOK   1280          // padded sequence (SEQ_LEN + 1)
#define NREAL  1279          // real tokens
#define DIMn   1024
#define TXT    256           // text length
#define BH     256           // Bn * Hn
#define HD     (NTOK * DHn)  // 81920 halfs per (b,h) plane
#define MQKV   (Bn * NTOK)   // 20480
#define MOUT   (Bn * NREAL)  // 20464
#define QSCALE 0.125f        // DH^-0.5

// ---------------------------------------------------------------------------
// Scratch (device globals: allocation-free)
// ---------------------------------------------------------------------------
__device__ __half g_qh[(size_t)BH * HD];
__device__ __half g_kh[(size_t)BH * HD];
__device__ __half g_vh[(size_t)BH * HD];
__device__ __half g_xh[(size_t)MQKV * DIMn];     // padded x in fp16
__device__ __half g_wqkvh[3 * DIMn * DIMn];      // w_qkv fp16
__device__ __half g_wouth[DIMn * DIMn];          // w_out fp16
__device__ __half g_oh[(size_t)MOUT * DIMn];     // attn out, de-interleaved fp16

// ---------------------------------------------------------------------------
// MMA / ldmatrix helpers
// ---------------------------------------------------------------------------
__device__ __forceinline__ void mma_f16(float c[4], const unsigned a[4],
                                        const unsigned b[2]) {
    asm volatile(
        "mma.sync.aligned.m16n8k16.row.col.f32.f16.f16.f32 "
        "{%0,%1,%2,%3}, {%4,%5,%6,%7}, {%8,%9}, {%0,%1,%2,%3};\n"
        : "+f"(c[0]), "+f"(c[1]), "+f"(c[2]), "+f"(c[3])
        : "r"(a[0]), "r"(a[1]), "r"(a[2]), "r"(a[3]), "r"(b[0]), "r"(b[1]));
}
__device__ __forceinline__ void ldsm4(unsigned& r0, unsigned& r1,
                                      unsigned& r2, unsigned& r3, unsigned addr) {
    asm volatile("ldmatrix.sync.aligned.m8n8.x4.shared.b16 {%0,%1,%2,%3}, [%4];\n"
                 : "=r"(r0), "=r"(r1), "=r"(r2), "=r"(r3) : "r"(addr));
}
__device__ __forceinline__ void ldsm4t(unsigned& r0, unsigned& r1,
                                       unsigned& r2, unsigned& r3, unsigned addr) {
    asm volatile("ldmatrix.sync.aligned.m8n8.x4.trans.shared.b16 {%0,%1,%2,%3}, [%4];\n"
                 : "=r"(r0), "=r"(r1), "=r"(r2), "=r"(r3) : "r"(addr));
}

// Attention/GEMM tiles: 128B rows (64 halfs), chunk c (0..7)
__device__ __forceinline__ unsigned off16(int row, int c) {
    return (unsigned)(row * 128 + ((c ^ (row & 7)) << 4));
}
// Score matrix S: 640B rows (320 halfs), chunk swizzle within 8-chunk groups
__device__ __forceinline__ unsigned sidx16(int row, int c) {
    int cc = (c & ~7) | ((c & 7) ^ (row & 7));
    return (unsigned)(row * 640 + (cc << 4));
}
__device__ __forceinline__ char* sptr(char* base, int row, int col) {
    return base + sidx16(row, col >> 3) + (col & 7) * 2;
}

__device__ __forceinline__ void cp16(unsigned dst, const void* src, bool v) {
    int sz = v ? 16 : 0;
    asm volatile("cp.async.cg.shared.global [%0], [%1], 16, %2;\n"
                 :: "r"(dst), "l"(src), "r"(sz) : "memory");
}
__device__ __forceinline__ void cp_commit() {
    asm volatile("cp.async.commit_group;\n" ::: "memory");
}
__device__ __forceinline__ void cp_wait1() {
    asm volatile("cp.async.wait_group 1;\n" ::: "memory");
}

// ---------------------------------------------------------------------------
// fp16 HGEMM v3: 128x128 CTA tile, BK=64 per sync, 3-stage cp.async pipeline
// (96KB dyn smem, 2 CTAs/SM). ROLLING fragment reload: b[p] is re-loaded for
// the next k16 immediately after its last consuming mma, so ldsm latency
// overlaps the mma stream (no extra registers).
// Smem-staged coalesced epilogues.
// EPI=0: fp16 to g_qh/g_kh/g_vh head layout (block-constant which/scale).
// EPI=1: fp32 out + bias.
// ---------------------------------------------------------------------------
#define HG_STG  32768
#define HG_SMEM (3 * HG_STG)   // 98304

template <int EPI>
__global__ __launch_bounds__(256, 2) void hgemm_kernel(
    const __half* __restrict__ A, const __half* __restrict__ B,
    const float* __restrict__ bias, float* __restrict__ out, int Mv)
{
    extern __shared__ __align__(16) __half gsm[];
    const unsigned smbase = (unsigned)__cvta_generic_to_shared(gsm);

    const int tid = threadIdx.x;
    const int m0 = blockIdx.y * 128;
    const int n0 = blockIdx.x * 128;

    auto load_stage = [&](int s, int kc) {
        const unsigned sa = smbase + s * HG_STG;
        const int kofs = kc * 64;
#pragma unroll
        for (int r = 0; r < 4; r++) {
            const int id = tid + 256 * r;
            const int row = id >> 3, c = id & 7;
            cp16(sa + off16(row, c),
                 A + (size_t)(m0 + row) * DIMn + kofs + c * 8, (m0 + row) < Mv);
        }
#pragma unroll
        for (int r = 0; r < 4; r++) {
            const int id = tid + 256 * r;
            const int row = id >> 3, c = id & 7;
            cp16(sa + 16384 + off16(row, c),
                 B + (size_t)(n0 + row) * DIMn + kofs + c * 8, true);
        }
    };

    const int lane = tid & 31, warp = tid >> 5;
    const int wM = warp >> 1, wN = warp & 1;         // 4 x 2 warps, 32x64 tile
    const int aRow = wM * 32 + (lane & 15);
    const int aC   = lane >> 4;
    const int bRow = wN * 64 + (lane & 7) + ((lane >> 4) & 1) * 8;
    const int bC   = (lane >> 3) & 1;

    float c[2][8][4];
#pragma unroll
    for (int tm = 0; tm < 2; tm++)
#pragma unroll
        for (int tn = 0; tn < 8; tn++)
#pragma unroll
            for (int i = 0; i < 4; i++) c[tm][tn][i] = 0.f;

    load_stage(0, 0); cp_commit();
    load_stage(1, 1); cp_commit();

#pragma unroll 1
    for (int it = 0; it < 16; it++) {
        cp_wait1();
        __syncthreads();
        const int s = it - (it / 3) * 3;
        const unsigned sa = smbase + s * HG_STG;
        const unsigned sbB = sa + 16384;

        unsigned a[2][4], b[4][4];
        // fragment prologue for k16 = 0
#pragma unroll
        for (int tm = 0; tm < 2; tm++)
            ldsm4(a[tm][0], a[tm][1], a[tm][2], a[tm][3],
                  sa + off16(aRow + tm * 16, aC));
#pragma unroll
        for (int p = 0; p < 4; p++)
            ldsm4(b[p][0], b[p][1], b[p][2], b[p][3],
                  sbB + off16(bRow + p * 16, bC));

#pragma unroll
        for (int k16 = 0; k16 < 4; k16++) {
            const int nx = k16 + 1;
#pragma unroll
            for (int p = 0; p < 4; p++) {
                mma_f16(c[0][2 * p],     a[0], &b[p][0]);
                mma_f16(c[1][2 * p],     a[1], &b[p][0]);
                mma_f16(c[0][2 * p + 1], a[0], &b[p][2]);
                mma_f16(c[1][2 * p + 1], a[1], &b[p][2]);
                // b[p] fully consumed for this k16 -> reload for next k16
                if (nx < 4)
                    ldsm4(b[p][0], b[p][1], b[p][2], b[p][3],
                          sbB + off16(bRow + p * 16, nx * 2 + bC));
            }
            if (nx < 4) {
#pragma unroll
                for (int tm = 0; tm < 2; tm++)
                    ldsm4(a[tm][0], a[tm][1], a[tm][2], a[tm][3],
                          sa + off16(aRow + tm * 16, nx * 2 + aC));
            }
            if (k16 == 0 && it + 2 < 16) load_stage((it + 2) % 3, it + 2);
        }
        cp_commit();     // one group per iteration (may be empty near tail)
    }

    const int grp = lane >> 2, qd = lane & 3;
    __syncthreads();     // pipeline done; smem becomes epilogue staging

    if (EPI == 0) {
        // which/scale are block-constant (n0 is a multiple of 128)
        const int which = n0 >> 10;
        __half* dst = (which == 0) ? g_qh : ((which == 1) ? g_kh : g_vh);
        const float sc = (which == 0) ? QSCALE : 1.0f;
        __half* st = gsm;                 // 128 x 136 halfs (34816 B)
#pragma unroll
        for (int tm = 0; tm < 2; tm++)
#pragma unroll
            for (int hf = 0; hf < 2; hf++) {
                const int row = wM * 32 + tm * 16 + grp + hf * 8;
#pragma unroll
                for (int tn = 0; tn < 8; tn++) {
                    const int col = wN * 64 + tn * 8 + qd * 2;
                    __half2 hv = __floats2half2_rn(c[tm][tn][hf * 2 + 0] * sc,
                                                   c[tm][tn][hf * 2 + 1] * sc);
                    *(__half2*)(st + row * 136 + col) = hv;
                }
            }
        __syncthreads();
        const int r = tid >> 1, seg = tid & 1;
        const int mrow = m0 + r;
        if (mrow < Mv) {
            const int gcol = n0 + seg * 64;
            const int h = (gcol & 1023) >> 6;
            const int b_ = mrow / NTOK;
            const int n_ = mrow - b_ * NTOK;
            __half* base = dst + ((size_t)(b_ * Hn + h) * NTOK + n_) * DHn;
            const __half* src = st + r * 136 + seg * 64;
#pragma unroll
            for (int i = 0; i < 8; i++)
                *(uint4*)(base + i * 8) = *(const uint4*)(src + i * 8);
        }
    } else {
        float* st = (float*)gsm;          // 128 x 136 floats (69632 B)
#pragma unroll
        for (int tm = 0; tm < 2; tm++)
#pragma unroll
            for (int hf = 0; hf < 2; hf++) {
                const int row = wM * 32 + tm * 16 + grp + hf * 8;
#pragma unroll
                for (int tn = 0; tn < 8; tn++) {
                    const int col = wN * 64 + tn * 8 + qd * 2;
                    float2 v = make_float2(c[tm][tn][hf * 2 + 0],
                                           c[tm][tn][hf * 2 + 1]);
                    *(float2*)(st + row * 136 + col) = v;
                }
            }
        __syncthreads();
        const int r = tid >> 1, seg = tid & 1;
        const int mrow = m0 + r;
        if (mrow < Mv) {
            const float* src = st + r * 136 + seg * 64;
            const float* bsrc = bias + n0 + seg * 64;
            float* dstp = out + (size_t)mrow * DIMn + n0 + seg * 64;
#pragma unroll
            for (int i = 0; i < 16; i++) {
                float4 v = *(const float4*)(src + i * 4);
                float4 bb = *(const float4*)(bsrc + i * 4);
                v.x += bb.x; v.y += bb.y; v.z += bb.z; v.w += bb.w;
                *(float4*)(dstp + i * 4) = v;
            }
        }
    }
}

// ---------------------------------------------------------------------------
// Merged fp32 -> fp16 conversion kernel (x pad + w_qkv + w_out)
// ---------------------------------------------------------------------------
#define X_E4  (MQKV * DIMn / 4)
#define WQ_E4 (3 * DIMn * DIMn / 4)
#define WO_E4 (DIMn * DIMn / 4)
#define CVT_TOT (X_E4 + WQ_E4 + WO_E4)

__global__ __launch_bounds__(256) void cvt_all_kernel(
    const float* __restrict__ x, const float* __restrict__ wqkv,
    const float* __restrict__ wout)
{
    long i = (long)blockIdx.x * 256 + threadIdx.x;
    if (i >= CVT_TOT) return;
    float4 v;
    __half* dst;
    size_t e;
    if (i < X_E4) {
        e = (size_t)i * 4;
        int m = (int)(e >> 10);
        int col = (int)(e & 1023);
        int b = m / NTOK, n = m - b * NTOK;
        v = make_float4(0.f, 0.f, 0.f, 0.f);
        if (n < NREAL) v = *(const float4*)(x + ((size_t)b * NREAL + n) * DIMn + col);
        dst = g_xh;
    } else if (i < X_E4 + WQ_E4) {
        e = (size_t)(i - X_E4) * 4;
        v = *(const float4*)(wqkv + e);
        dst = g_wqkvh;
    } else {
        e = (size_t)(i - X_E4 - WQ_E4) * 4;
        v = *(const float4*)(wout + e);
        dst = g_wouth;
    }
    __half2 h0 = __floats2half2_rn(v.x, v.y);
    __half2 h1 = __floats2half2_rn(v.z, v.w);
    uint2 u;
    u.x = *(unsigned*)&h0;
    u.y = *(unsigned*)&h1;
    *(uint2*)(dst + e) = u;
}

// ---------------------------------------------------------------------------
// Fused tensor-core attention: cp.async ping-pong pipeline, vectorized
// softmax, smem-staged coalesced output (R11; measured).
// smem: Q[64][64] @0, KVbuf0 @8192, KVbuf1 @16384, S[64][320] @24576,
//       inv[64] @65536. Total 65792 B -> 3 CTAs/SM.
// ---------------------------------------------------------------------------
#define ATT_QOFF 0
#define ATT_B0   8192
#define ATT_B1   16384
#define ATT_SOFF 24576
#define ATT_IOFF 65536
#define ATT_SMEM 65792

__device__ __forceinline__ void att_cp_tile(unsigned dstbase, const __half* g,
                                            int tid) {
#pragma unroll
    for (int r = 0; r < 4; r++) {
        int id = tid + 128 * r;
        int row = id >> 3, c = id & 7;
        cp16(dstbase + off16(row, c), g + row * 64 + c * 8, true);
    }
}

__global__ __launch_bounds__(128) void attn_fused_kernel()
{
    extern __shared__ char sm[];
    const unsigned sb = (unsigned)__cvta_generic_to_shared(sm);
    float* invs = (float*)(sm + ATT_IOFF);

    const int bh = blockIdx.y;
    const int bx = blockIdx.x;
    const bool isText = (bx < 4);
    const int tid = threadIdx.x, lane = tid & 31, warp = tid >> 5;
    const int grp = lane >> 2, qd = lane & 3;

    const int qtok0 = isText ? bx * 64 : TXT + (bx - 4) * 64;

    const __half* qg = g_qh + (size_t)bh * HD + (size_t)qtok0 * DHn;
    const __half* kg = g_kh + (size_t)bh * HD;
    const __half* vg = g_vh + (size_t)bh * HD;

    const int nK = isText ? (bx + 1) : 5;
    const int total = 2 * nK;
    const int ncols = isText ? (qtok0 + 64) : (TXT + 32);

    auto tile_src = [&](int t) -> const __half* {
        if (t < nK) {
            if (isText || t < 4) return kg + (size_t)t * 64 * DHn;
            return kg + (size_t)qtok0 * DHn;
        }
        int v = t - nK;
        if (isText || v < 4) return vg + (size_t)v * 64 * DHn;
        return vg + (size_t)qtok0 * DHn;
    };

    att_cp_tile(sb + ATT_QOFF, qg, tid);
    att_cp_tile(sb + ATT_B0, tile_src(0), tid);
    cp_commit();
    att_cp_tile(sb + ATT_B1, tile_src(1), tid);
    cp_commit();

    const int aRow = warp * 16 + (lane & 15);
    const int aC   = lane >> 4;
    const int bRow = (lane & 7) + ((lane >> 4) & 1) * 8;
    const int bC   = (lane >> 3) & 1;
    const int kb   = (warp >> 1) * 32;

    float co[8][4];
#pragma unroll
    for (int tn = 0; tn < 8; tn++)
#pragma unroll
        for (int i = 0; i < 4; i++) co[tn][i] = 0.f;

#pragma unroll 1
    for (int t = 0; t < total; t++) {
        cp_wait1();
        __syncthreads();

        if (t == nK) {
            // ---- vectorized softmax: 2 threads/row, uint4 chunks ----
            const int row = tid >> 1, hv = tid & 1;
            const int nch = ncols >> 4;
            const int ch0 = hv * nch;
            char* srow = sm + ATT_SOFF;
            float mx = -FLT_MAX;
#pragma unroll 2
            for (int ch = ch0; ch < ch0 + nch; ch++) {
                uint4 v = *(uint4*)(srow + sidx16(row, ch));
                const __half2* hp = (const __half2*)&v;
#pragma unroll
                for (int i = 0; i < 4; i++) {
                    float2 f = __half22float2(hp[i]);
                    mx = fmaxf(mx, fmaxf(f.x, f.y));
                }
            }
            mx = fmaxf(mx, __shfl_xor_sync(0xffffffffu, mx, 1));
            float sum = 0.f;
#pragma unroll 2
            for (int ch = ch0; ch < ch0 + nch; ch++) {
                char* p = srow + sidx16(row, ch);
                uint4 v = *(uint4*)p;
                __half2* hp = (__half2*)&v;
#pragma unroll
                for (int i = 0; i < 4; i++) {
                    float2 f = __half22float2(hp[i]);
                    f.x = __expf(f.x - mx);
                    f.y = __expf(f.y - mx);
                    sum += f.x + f.y;
                    hp[i] = __floats2half2_rn(f.x, f.y);
                }
                *(uint4*)p = v;
            }
            sum += __shfl_xor_sync(0xffffffffu, sum, 1);
            if (hv == 0) invs[row] = 1.f / sum;
            __syncthreads();
        }

        const unsigned kvb = sb + ((t & 1) ? ATT_B1 : ATT_B0);

        if (t < nK) {
            const bool imgTile = (!isText) && (t == 4);
            if (!imgTile) {
                const int j0 = t * 64;
                float cs[8][4];
#pragma unroll
                for (int tn = 0; tn < 8; tn++)
#pragma unroll
                    for (int i = 0; i < 4; i++) cs[tn][i] = 0.f;
#pragma unroll
                for (int k16 = 0; k16 < 4; k16++) {
                    unsigned a[4], b[4][4];
                    ldsm4(a[0], a[1], a[2], a[3],
                          sb + ATT_QOFF + off16(aRow, k16 * 2 + aC));
#pragma unroll
                    for (int p = 0; p < 4; p++)
                        ldsm4(b[p][0], b[p][1], b[p][2], b[p][3],
                              kvb + off16(p * 16 + bRow, k16 * 2 + bC));
#pragma unroll
                    for (int tn = 0; tn < 8; tn++)
                        mma_f16(cs[tn], a, &b[tn >> 1][(tn & 1) * 2]);
                }
                const bool diag = isText && (t == nK - 1);
#pragma unroll
                for (int tn = 0; tn < 8; tn++) {
#pragma unroll
                    for (int hf = 0; hf < 2; hf++) {
                        const int row = warp * 16 + grp + hf * 8;
                        const int col = j0 + tn * 8 + qd * 2;
                        float v0 = cs[tn][hf * 2 + 0];
                        float v1 = cs[tn][hf * 2 + 1];
                        if (diag) {
                            const int qglob = qtok0 + row;
                            if (col > qglob)     v0 = -1e30f;
                            if (col + 1 > qglob) v1 = -1e30f;
                        }
                        __half2 h = __floats2half2_rn(v0, v1);
                        *(unsigned*)sptr(sm + ATT_SOFF, row, col) = *(unsigned*)&h;
                    }
                }
            } else {
                float cs[4][4];
#pragma unroll
                for (int tn = 0; tn < 4; tn++)
#pragma unroll
                    for (int i = 0; i < 4; i++) cs[tn][i] = 0.f;
#pragma unroll
                for (int k16 = 0; k16 < 4; k16++) {
                    unsigned a[4], b[2][4];
                    ldsm4(a[0], a[1], a[2], a[3],
                          sb + ATT_QOFF + off16(aRow, k16 * 2 + aC));
#pragma unroll
                    for (int p = 0; p < 2; p++)
                        ldsm4(b[p][0], b[p][1], b[p][2], b[p][3],
                              kvb + off16(kb + p * 16 + bRow, k16 * 2 + bC));
#pragma unroll
                    for (int tn = 0; tn < 4; tn++)
                        mma_f16(cs[tn], a, &b[tn >> 1][(tn & 1) * 2]);
                }
#pragma unroll
                for (int tn = 0; tn < 4; tn++) {
#pragma unroll
                    for (int hf = 0; hf < 2; hf++) {
                        const int row = warp * 16 + grp + hf * 8;
                        const int qlocal = row & 31;
                        const int j = tn * 8 + qd * 2;
                        float v0 = (j     <= qlocal) ? cs[tn][hf * 2 + 0] : -1e30f;
                        float v1 = (j + 1 <= qlocal) ? cs[tn][hf * 2 + 1] : -1e30f;
                        __half2 h = __floats2half2_rn(v0, v1);
                        *(unsigned*)sptr(sm + ATT_SOFF, row, TXT + j) = *(unsigned*)&h;
                    }
                }
            }
        } else {
            const int v = t - nK;
            const bool imgTile = (!isText) && (v == 4);
            if (!imgTile) {
                const int j0 = v * 64;
#pragma unroll
                for (int k16 = 0; k16 < 4; k16++) {
                    unsigned a[4], b[4][4];
                    ldsm4(a[0], a[1], a[2], a[3],
                          sb + ATT_SOFF + sidx16(aRow, (j0 >> 3) + k16 * 2 + aC));
#pragma unroll
                    for (int n16 = 0; n16 < 4; n16++)
                        ldsm4t(b[n16][0], b[n16][1], b[n16][2], b[n16][3],
                               kvb + off16(k16 * 16 + (lane & 15),
                                           n16 * 2 + (lane >> 4)));
#pragma unroll
                    for (int tn = 0; tn < 8; tn++)
                        mma_f16(co[tn], a, &b[tn >> 1][(tn & 1) * 2]);
                }
            } else {
#pragma unroll
                for (int k16 = 0; k16 < 2; k16++) {
                    unsigned a[4], b[4][4];
                    ldsm4(a[0], a[1], a[2], a[3],
                          sb + ATT_SOFF + sidx16(aRow, (TXT >> 3) + k16 * 2 + aC));
#pragma unroll
                    for (int n16 = 0; n16 < 4; n16++)
                        ldsm4t(b[n16][0], b[n16][1], b[n16][2], b[n16][3],
                               kvb + off16(kb + k16 * 16 + (lane & 15),
                                           n16 * 2 + (lane >> 4)));
#pragma unroll
                    for (int tn = 0; tn < 8; tn++)
                        mma_f16(co[tn], a, &b[tn >> 1][(tn & 1) * 2]);
                }
            }
        }

        __syncthreads();
        if (t + 2 < total)
            att_cp_tile(sb + ((t & 1) ? ATT_B1 : ATT_B0), tile_src(t + 2), tid);
        cp_commit();
    }

    // ---- output: stage (co * inv) into S region, then coalesced stores ----
    const float inv0 = invs[warp * 16 + grp];
    const float inv1 = invs[warp * 16 + grp + 8];
    __half* st = (__half*)(sm + ATT_SOFF);    // 64 x 72 halfs
#pragma unroll
    for (int tn = 0; tn < 8; tn++) {
#pragma unroll
        for (int hf = 0; hf < 2; hf++) {
            const int row = warp * 16 + grp + hf * 8;
            const int col = tn * 8 + qd * 2;
            const float inv = hf ? inv1 : inv0;
            __half2 h = __floats2half2_rn(co[tn][hf * 2 + 0] * inv,
                                          co[tn][hf * 2 + 1] * inv);
            *(__half2*)(st + row * 72 + col) = h;
        }
    }
    __syncthreads();
    {
        const int row = tid >> 1, seg = tid & 1;
        const int token = qtok0 + row;
        if (token < NREAL) {
            const int b_ = bh >> 4, h_ = bh & 15;
            const int m = b_ * NREAL + token;
            __half* dstp = g_oh + (size_t)m * DIMn + h_ * 64 + seg * 32;
            const __half* srcp = st + row * 72 + seg * 32;
#pragma unroll
            for (int i = 0; i < 4; i++)
                *(uint4*)(dstp + i * 8) = *(const uint4*)(srcp + i * 8);
        }
    }
}

// ---------------------------------------------------------------------------
// Launch
// ---------------------------------------------------------------------------
extern "C" void kernel_launch(void* const* d_in, const int* in_sizes, int n_in,
                              void* d_out, int out_size)
{
    (void)in_sizes; (void)n_in; (void)out_size;
    const float* x     = (const float*)d_in[0];
    const float* w_qkv = (const float*)d_in[1];
    const float* w_out = (const float*)d_in[2];
    const float* b_out = (const float*)d_in[3];
    float* out = (float*)d_out;

    cudaFuncSetAttribute(attn_fused_kernel,
                         cudaFuncAttributeMaxDynamicSharedMemorySize, ATT_SMEM);
    cudaFuncSetAttribute(hgemm_kernel<0>,
                         cudaFuncAttributeMaxDynamicSharedMemorySize, HG_SMEM);
    cudaFuncSetAttribute(hgemm_kernel<1>,
                         cudaFuncAttributeMaxDynamicSharedMemorySize, HG_SMEM);

    void* p_xh;    cudaGetSymbolAddress(&p_xh, g_xh);
    void* p_wqkv;  cudaGetSymbolAddress(&p_wqkv, g_wqkvh);
    void* p_wout;  cudaGetSymbolAddress(&p_wout, g_wouth);
    void* p_oh;    cudaGetSymbolAddress(&p_oh, g_oh);

    // 0) fp32 -> fp16 conversions (single merged kernel)
    cvt_all_kernel<<<(CVT_TOT + 255) / 256, 256>>>(x, w_qkv, w_out);

    // 1) QKV projection (fp16 tensor cores) into fp16 head-layout scratch
    hgemm_kernel<0><<<dim3(24, 160), 256, HG_SMEM>>>(
        (const __half*)p_xh, (const __half*)p_wqkv, nullptr, nullptr, MQKV);

    // 2) fused text + axial image attention (pipelined tile loads)
    attn_fused_kernel<<<dim3(20, 256), 128, ATT_SMEM>>>();

    // 3) output projection + bias (fp16 tensor cores)
    hgemm_kernel<1><<<dim3(8, 160), 256, HG_SMEM>>>(
        (const __half*)p_oh, (const __half*)p_wout, b_out, out, MOUT);
}

// round 13
// speedup vs baseline: 1.0242x; 1.0242x over previous
#include <cuda_runtime.h>
#include <cuda_fp16.h>
#include <float.h>

// ---------------------------------------------------------------------------
// Problem constants
// ---------------------------------------------------------------------------
#define Bn     16
#define Hn     16
#define DHn    64
#define NTOK   1280          // padded sequence (SEQ_LEN + 1)
#define NREAL  1279          // real tokens
#define DIMn   1024
#define TXT    256           // text length
#define BH     256           // Bn * Hn
#define HD     (NTOK * DHn)  // 81920 halfs per (b,h) plane
#define MQKV   (Bn * NTOK)   // 20480
#define MOUT   (Bn * NREAL)  // 20464
#define QSCALE 0.125f        // DH^-0.5

// ---------------------------------------------------------------------------
// Scratch (device globals: allocation-free)
// ---------------------------------------------------------------------------
__device__ __half g_qh[(size_t)BH * HD];
__device__ __half g_kh[(size_t)BH * HD];
__device__ __half g_vh[(size_t)BH * HD];
__device__ __half g_xh[(size_t)MQKV * DIMn];     // padded x in fp16
__device__ __half g_wqkvh[3 * DIMn * DIMn];      // w_qkv fp16
__device__ __half g_wouth[DIMn * DIMn];          // w_out fp16
__device__ __half g_oh[(size_t)MOUT * DIMn];     // attn out, de-interleaved fp16

// ---------------------------------------------------------------------------
// MMA / ldmatrix helpers
// ---------------------------------------------------------------------------
__device__ __forceinline__ void mma_f16(float c[4], const unsigned a[4],
                                        const unsigned b[2]) {
    asm volatile(
        "mma.sync.aligned.m16n8k16.row.col.f32.f16.f16.f32 "
        "{%0,%1,%2,%3}, {%4,%5,%6,%7}, {%8,%9}, {%0,%1,%2,%3};\n"
        : "+f"(c[0]), "+f"(c[1]), "+f"(c[2]), "+f"(c[3])
        : "r"(a[0]), "r"(a[1]), "r"(a[2]), "r"(a[3]), "r"(b[0]), "r"(b[1]));
}
__device__ __forceinline__ void ldsm4(unsigned& r0, unsigned& r1,
                                      unsigned& r2, unsigned& r3, unsigned addr) {
    asm volatile("ldmatrix.sync.aligned.m8n8.x4.shared.b16 {%0,%1,%2,%3}, [%4];\n"
                 : "=r"(r0), "=r"(r1), "=r"(r2), "=r"(r3) : "r"(addr));
}
__device__ __forceinline__ void ldsm4t(unsigned& r0, unsigned& r1,
                                       unsigned& r2, unsigned& r3, unsigned addr) {
    asm volatile("ldmatrix.sync.aligned.m8n8.x4.trans.shared.b16 {%0,%1,%2,%3}, [%4];\n"
                 : "=r"(r0), "=r"(r1), "=r"(r2), "=r"(r3) : "r"(addr));
}

// Attention/GEMM tiles: 128B rows (64 halfs), chunk c (0..7)
__device__ __forceinline__ unsigned off16(int row, int c) {
    return (unsigned)(row * 128 + ((c ^ (row & 7)) << 4));
}
// Score matrix S: 640B rows (320 halfs), chunk swizzle within 8-chunk groups
__device__ __forceinline__ unsigned sidx16(int row, int c) {
    int cc = (c & ~7) | ((c & 7) ^ (row & 7));
    return (unsigned)(row * 640 + (cc << 4));
}
__device__ __forceinline__ char* sptr(char* base, int row, int col) {
    return base + sidx16(row, col >> 3) + (col & 7) * 2;
}

__device__ __forceinline__ void cp16(unsigned dst, const void* src, bool v) {
    int sz = v ? 16 : 0;
    asm volatile("cp.async.cg.shared.global [%0], [%1], 16, %2;\n"
                 :: "r"(dst), "l"(src), "r"(sz) : "memory");
}
__device__ __forceinline__ void cp_commit() {
    asm volatile("cp.async.commit_group;\n" ::: "memory");
}
__device__ __forceinline__ void cp_wait1() {
    asm volatile("cp.async.wait_group 1;\n" ::: "memory");
}

// ---------------------------------------------------------------------------
// fp16 HGEMM (exact R11 version; measured total 615us).
// 128x128 CTA tile, BK=64 per sync, 3-stage cp.async pipeline
// (96KB dyn smem, 2 CTAs/SM), fragments single-buffered across 4 k16 steps.
// Smem-staged coalesced epilogues.
// EPI=0: fp16 to g_qh/g_kh/g_vh head layout (block-constant which/scale).
// EPI=1: fp32 out + bias.
// ---------------------------------------------------------------------------
#define HG_STG  32768
#define HG_SMEM (3 * HG_STG)   // 98304

template <int EPI>
__global__ __launch_bounds__(256, 2) void hgemm_kernel(
    const __half* __restrict__ A, const __half* __restrict__ B,
    const float* __restrict__ bias, float* __restrict__ out, int Mv)
{
    extern __shared__ __align__(16) __half gsm[];
    const unsigned smbase = (unsigned)__cvta_generic_to_shared(gsm);

    const int tid = threadIdx.x;
    const int m0 = blockIdx.y * 128;
    const int n0 = blockIdx.x * 128;

    auto load_stage = [&](int s, int kc) {
        const unsigned sa = smbase + s * HG_STG;
        const int kofs = kc * 64;
#pragma unroll
        for (int r = 0; r < 4; r++) {
            const int id = tid + 256 * r;
            const int row = id >> 3, c = id & 7;
            cp16(sa + off16(row, c),
                 A + (size_t)(m0 + row) * DIMn + kofs + c * 8, (m0 + row) < Mv);
        }
#pragma unroll
        for (int r = 0; r < 4; r++) {
            const int id = tid + 256 * r;
            const int row = id >> 3, c = id & 7;
            cp16(sa + 16384 + off16(row, c),
                 B + (size_t)(n0 + row) * DIMn + kofs + c * 8, true);
        }
    };

    const int lane = tid & 31, warp = tid >> 5;
    const int wM = warp >> 1, wN = warp & 1;         // 4 x 2 warps, 32x64 tile
    const int aRow = wM * 32 + (lane & 15);
    const int aC   = lane >> 4;
    const int bRow = wN * 64 + (lane & 7) + ((lane >> 4) & 1) * 8;
    const int bC   = (lane >> 3) & 1;

    float c[2][8][4];
#pragma unroll
    for (int tm = 0; tm < 2; tm++)
#pragma unroll
        for (int tn = 0; tn < 8; tn++)
#pragma unroll
            for (int i = 0; i < 4; i++) c[tm][tn][i] = 0.f;

    load_stage(0, 0); cp_commit();
    load_stage(1, 1); cp_commit();

#pragma unroll 1
    for (int it = 0; it < 16; it++) {
        cp_wait1();
        __syncthreads();
        const int s = it - (it / 3) * 3;
        const unsigned sa = smbase + s * HG_STG;
        const unsigned sbB = sa + 16384;

#pragma unroll
        for (int k16 = 0; k16 < 4; k16++) {
            unsigned a[2][4], b[4][4];
#pragma unroll
            for (int tm = 0; tm < 2; tm++)
                ldsm4(a[tm][0], a[tm][1], a[tm][2], a[tm][3],
                      sa + off16(aRow + tm * 16, k16 * 2 + aC));
#pragma unroll
            for (int p = 0; p < 4; p++)
                ldsm4(b[p][0], b[p][1], b[p][2], b[p][3],
                      sbB + off16(bRow + p * 16, k16 * 2 + bC));
#pragma unroll
            for (int tm = 0; tm < 2; tm++)
#pragma unroll
                for (int tn = 0; tn < 8; tn++)
                    mma_f16(c[tm][tn], a[tm], &b[tn >> 1][(tn & 1) * 2]);
            if (k16 == 0 && it + 2 < 16) load_stage((it + 2) % 3, it + 2);
        }
        cp_commit();     // one group per iteration (may be empty near tail)
    }

    const int grp = lane >> 2, qd = lane & 3;
    __syncthreads();     // pipeline done; smem becomes epilogue staging

    if (EPI == 0) {
        // which/scale are block-constant (n0 is a multiple of 128)
        const int which = n0 >> 10;
        __half* dst = (which == 0) ? g_qh : ((which == 1) ? g_kh : g_vh);
        const float sc = (which == 0) ? QSCALE : 1.0f;
        __half* st = gsm;                 // 128 x 136 halfs (34816 B)
#pragma unroll
        for (int tm = 0; tm < 2; tm++)
#pragma unroll
            for (int hf = 0; hf < 2; hf++) {
                const int row = wM * 32 + tm * 16 + grp + hf * 8;
#pragma unroll
                for (int tn = 0; tn < 8; tn++) {
                    const int col = wN * 64 + tn * 8 + qd * 2;
                    __half2 hv = __floats2half2_rn(c[tm][tn][hf * 2 + 0] * sc,
                                                   c[tm][tn][hf * 2 + 1] * sc);
                    *(__half2*)(st + row * 136 + col) = hv;
                }
            }
        __syncthreads();
        const int r = tid >> 1, seg = tid & 1;
        const int mrow = m0 + r;
        if (mrow < Mv) {
            const int gcol = n0 + seg * 64;
            const int h = (gcol & 1023) >> 6;
            const int b_ = mrow / NTOK;
            const int n_ = mrow - b_ * NTOK;
            __half* base = dst + ((size_t)(b_ * Hn + h) * NTOK + n_) * DHn;
            const __half* src = st + r * 136 + seg * 64;
#pragma unroll
            for (int i = 0; i < 8; i++)
                *(uint4*)(base + i * 8) = *(const uint4*)(src + i * 8);
        }
    } else {
        float* st = (float*)gsm;          // 128 x 136 floats (69632 B)
#pragma unroll
        for (int tm = 0; tm < 2; tm++)
#pragma unroll
            for (int hf = 0; hf < 2; hf++) {
                const int row = wM * 32 + tm * 16 + grp + hf * 8;
#pragma unroll
                for (int tn = 0; tn < 8; tn++) {
                    const int col = wN * 64 + tn * 8 + qd * 2;
                    float2 v = make_float2(c[tm][tn][hf * 2 + 0],
                                           c[tm][tn][hf * 2 + 1]);
                    *(float2*)(st + row * 136 + col) = v;
                }
            }
        __syncthreads();
        const int r = tid >> 1, seg = tid & 1;
        const int mrow = m0 + r;
        if (mrow < Mv) {
            const float* src = st + r * 136 + seg * 64;
            const float* bsrc = bias + n0 + seg * 64;
            float* dstp = out + (size_t)mrow * DIMn + n0 + seg * 64;
#pragma unroll
            for (int i = 0; i < 16; i++) {
                float4 v = *(const float4*)(src + i * 4);
                float4 bb = *(const float4*)(bsrc + i * 4);
                v.x += bb.x; v.y += bb.y; v.z += bb.z; v.w += bb.w;
                *(float4*)(dstp + i * 4) = v;
            }
        }
    }
}

// ---------------------------------------------------------------------------
// Merged fp32 -> fp16 conversion kernel (x pad + w_qkv + w_out)
// ---------------------------------------------------------------------------
#define X_E4  (MQKV * DIMn / 4)
#define WQ_E4 (3 * DIMn * DIMn / 4)
#define WO_E4 (DIMn * DIMn / 4)
#define CVT_TOT (X_E4 + WQ_E4 + WO_E4)

__global__ __launch_bounds__(256) void cvt_all_kernel(
    const float* __restrict__ x, const float* __restrict__ wqkv,
    const float* __restrict__ wout)
{
    long i = (long)blockIdx.x * 256 + threadIdx.x;
    if (i >= CVT_TOT) return;
    float4 v;
    __half* dst;
    size_t e;
    if (i < X_E4) {
        e = (size_t)i * 4;
        int m = (int)(e >> 10);
        int col = (int)(e & 1023);
        int b = m / NTOK, n = m - b * NTOK;
        v = make_float4(0.f, 0.f, 0.f, 0.f);
        if (n < NREAL) v = *(const float4*)(x + ((size_t)b * NREAL + n) * DIMn + col);
        dst = g_xh;
    } else if (i < X_E4 + WQ_E4) {
        e = (size_t)(i - X_E4) * 4;
        v = *(const float4*)(wqkv + e);
        dst = g_wqkvh;
    } else {
        e = (size_t)(i - X_E4 - WQ_E4) * 4;
        v = *(const float4*)(wout + e);
        dst = g_wouth;
    }
    __half2 h0 = __floats2half2_rn(v.x, v.y);
    __half2 h1 = __floats2half2_rn(v.z, v.w);
    uint2 u;
    u.x = *(unsigned*)&h0;
    u.y = *(unsigned*)&h1;
    *(uint2*)(dst + e) = u;
}

// ---------------------------------------------------------------------------
// Fused tensor-core attention (R11 math) with LPT block ordering:
// bx 0..15 = image row-pairs (10 tiles, longest) FIRST, bx 16..19 = text.
// smem: Q[64][64] @0, KVbuf0 @8192, KVbuf1 @16384, S[64][320] @24576,
//       inv[64] @65536. Total 65792 B -> 3 CTAs/SM.
// ---------------------------------------------------------------------------
#define ATT_QOFF 0
#define ATT_B0   8192
#define ATT_B1   16384
#define ATT_SOFF 24576
#define ATT_IOFF 65536
#define ATT_SMEM 65792

__device__ __forceinline__ void att_cp_tile(unsigned dstbase, const __half* g,
                                            int tid) {
#pragma unroll
    for (int r = 0; r < 4; r++) {
        int id = tid + 128 * r;
        int row = id >> 3, c = id & 7;
        cp16(dstbase + off16(row, c), g + row * 64 + c * 8, true);
    }
}

__global__ __launch_bounds__(128) void attn_fused_kernel()
{
    extern __shared__ char sm[];
    const unsigned sb = (unsigned)__cvta_generic_to_shared(sm);
    float* invs = (float*)(sm + ATT_IOFF);

    const int bh = blockIdx.y;
    const int bx = blockIdx.x;
    // LPT ordering: image blocks (longest) first
    const bool isText = (bx >= 16);
    const int tid = threadIdx.x, lane = tid & 31, warp = tid >> 5;
    const int grp = lane >> 2, qd = lane & 3;

    const int tIdx = bx - 16;                 // text tile index 0..3
    const int qtok0 = isText ? tIdx * 64 : TXT + bx * 64;

    const __half* qg = g_qh + (size_t)bh * HD + (size_t)qtok0 * DHn;
    const __half* kg = g_kh + (size_t)bh * HD;
    const __half* vg = g_vh + (size_t)bh * HD;

    const int nK = isText ? (tIdx + 1) : 5;
    const int total = 2 * nK;
    const int ncols = isText ? (qtok0 + 64) : (TXT + 32);

    auto tile_src = [&](int t) -> const __half* {
        if (t < nK) {
            if (isText || t < 4) return kg + (size_t)t * 64 * DHn;
            return kg + (size_t)qtok0 * DHn;
        }
        int v = t - nK;
        if (isText || v < 4) return vg + (size_t)v * 64 * DHn;
        return vg + (size_t)qtok0 * DHn;
    };

    att_cp_tile(sb + ATT_QOFF, qg, tid);
    att_cp_tile(sb + ATT_B0, tile_src(0), tid);
    cp_commit();
    att_cp_tile(sb + ATT_B1, tile_src(1), tid);
    cp_commit();

    const int aRow = warp * 16 + (lane & 15);
    const int aC   = lane >> 4;
    const int bRow = (lane & 7) + ((lane >> 4) & 1) * 8;
    const int bC   = (lane >> 3) & 1;
    const int kb   = (warp >> 1) * 32;

    float co[8][4];
#pragma unroll
    for (int tn = 0; tn < 8; tn++)
#pragma unroll
        for (int i = 0; i < 4; i++) co[tn][i] = 0.f;

#pragma unroll 1
    for (int t = 0; t < total; t++) {
        cp_wait1();
        __syncthreads();

        if (t == nK) {
            // ---- vectorized softmax: 2 threads/row, uint4 chunks ----
            const int row = tid >> 1, hv = tid & 1;
            const int nch = ncols >> 4;
            const int ch0 = hv * nch;
            char* srow = sm + ATT_SOFF;
            float mx = -FLT_MAX;
#pragma unroll 2
            for (int ch = ch0; ch < ch0 + nch; ch++) {
                uint4 v = *(uint4*)(srow + sidx16(row, ch));
                const __half2* hp = (const __half2*)&v;
#pragma unroll
                for (int i = 0; i < 4; i++) {
                    float2 f = __half22float2(hp[i]);
                    mx = fmaxf(mx, fmaxf(f.x, f.y));
                }
            }
            mx = fmaxf(mx, __shfl_xor_sync(0xffffffffu, mx, 1));
            float sum = 0.f;
#pragma unroll 2
            for (int ch = ch0; ch < ch0 + nch; ch++) {
                char* p = srow + sidx16(row, ch);
                uint4 v = *(uint4*)p;
                __half2* hp = (__half2*)&v;
#pragma unroll
                for (int i = 0; i < 4; i++) {
                    float2 f = __half22float2(hp[i]);
                    f.x = __expf(f.x - mx);
                    f.y = __expf(f.y - mx);
                    sum += f.x + f.y;
                    hp[i] = __floats2half2_rn(f.x, f.y);
                }
                *(uint4*)p = v;
            }
            sum += __shfl_xor_sync(0xffffffffu, sum, 1);
            if (hv == 0) invs[row] = 1.f / sum;
            __syncthreads();
        }

        const unsigned kvb = sb + ((t & 1) ? ATT_B1 : ATT_B0);

        if (t < nK) {
            const bool imgTile = (!isText) && (t == 4);
            if (!imgTile) {
                const int j0 = t * 64;
                float cs[8][4];
#pragma unroll
                for (int tn = 0; tn < 8; tn++)
#pragma unroll
                    for (int i = 0; i < 4; i++) cs[tn][i] = 0.f;
#pragma unroll
                for (int k16 = 0; k16 < 4; k16++) {
                    unsigned a[4], b[4][4];
                    ldsm4(a[0], a[1], a[2], a[3],
                          sb + ATT_QOFF + off16(aRow, k16 * 2 + aC));
#pragma unroll
                    for (int p = 0; p < 4; p++)
                        ldsm4(b[p][0], b[p][1], b[p][2], b[p][3],
                              kvb + off16(p * 16 + bRow, k16 * 2 + bC));
#pragma unroll
                    for (int tn = 0; tn < 8; tn++)
                        mma_f16(cs[tn], a, &b[tn >> 1][(tn & 1) * 2]);
                }
                const bool diag = isText && (t == nK - 1);
#pragma unroll
                for (int tn = 0; tn < 8; tn++) {
#pragma unroll
                    for (int hf = 0; hf < 2; hf++) {
                        const int row = warp * 16 + grp + hf * 8;
                        const int col = j0 + tn * 8 + qd * 2;
                        float v0 = cs[tn][hf * 2 + 0];
                        float v1 = cs[tn][hf * 2 + 1];
                        if (diag) {
                            const int qglob = qtok0 + row;
                            if (col > qglob)     v0 = -1e30f;
                            if (col + 1 > qglob) v1 = -1e30f;
                        }
                        __half2 h = __floats2half2_rn(v0, v1);
                        *(unsigned*)sptr(sm + ATT_SOFF, row, col) = *(unsigned*)&h;
                    }
                }
            } else {
                float cs[4][4];
#pragma unroll
                for (int tn = 0; tn < 4; tn++)
#pragma unroll
                    for (int i = 0; i < 4; i++) cs[tn][i] = 0.f;
#pragma unroll
                for (int k16 = 0; k16 < 4; k16++) {
                    unsigned a[4], b[2][4];
                    ldsm4(a[0], a[1], a[2], a[3],
                          sb + ATT_QOFF + off16(aRow, k16 * 2 + aC));
#pragma unroll
                    for (int p = 0; p < 2; p++)
                        ldsm4(b[p][0], b[p][1], b[p][2], b[p][3],
                              kvb + off16(kb + p * 16 + bRow, k16 * 2 + bC));
#pragma unroll
                    for (int tn = 0; tn < 4; tn++)
                        mma_f16(cs[tn], a, &b[tn >> 1][(tn & 1) * 2]);
                }
#pragma unroll
                for (int tn = 0; tn < 4; tn++) {
#pragma unroll
                    for (int hf = 0; hf < 2; hf++) {
                        const int row = warp * 16 + grp + hf * 8;
                        const int qlocal = row & 31;
                        const int j = tn * 8 + qd * 2;
                        float v0 = (j     <= qlocal) ? cs[tn][hf * 2 + 0] : -1e30f;
                        float v1 = (j + 1 <= qlocal) ? cs[tn][hf * 2 + 1] : -1e30f;
                        __half2 h = __floats2half2_rn(v0, v1);
                        *(unsigned*)sptr(sm + ATT_SOFF, row, TXT + j) = *(unsigned*)&h;
                    }
                }
            }
        } else {
            const int v = t - nK;
            const bool imgTile = (!isText) && (v == 4);
            if (!imgTile) {
                const int j0 = v * 64;
#pragma unroll
                for (int k16 = 0; k16 < 4; k16++) {
                    unsigned a[4], b[4][4];
                    ldsm4(a[0], a[1], a[2], a[3],
                          sb + ATT_SOFF + sidx16(aRow, (j0 >> 3) + k16 * 2 + aC));
#pragma unroll
                    for (int n16 = 0; n16 < 4; n16++)
                        ldsm4t(b[n16][0], b[n16][1], b[n16][2], b[n16][3],
                               kvb + off16(k16 * 16 + (lane & 15),
                                           n16 * 2 + (lane >> 4)));
#pragma unroll
                    for (int tn = 0; tn < 8; tn++)
                        mma_f16(co[tn], a, &b[tn >> 1][(tn & 1) * 2]);
                }
            } else {
#pragma unroll
                for (int k16 = 0; k16 < 2; k16++) {
                    unsigned a[4], b[4][4];
                    ldsm4(a[0], a[1], a[2], a[3],
                          sb + ATT_SOFF + sidx16(aRow, (TXT >> 3) + k16 * 2 + aC));
#pragma unroll
                    for (int n16 = 0; n16 < 4; n16++)
                        ldsm4t(b[n16][0], b[n16][1], b[n16][2], b[n16][3],
                               kvb + off16(kb + k16 * 16 + (lane & 15),
                                           n16 * 2 + (lane >> 4)));
#pragma unroll
                    for (int tn = 0; tn < 8; tn++)
                        mma_f16(co[tn], a, &b[tn >> 1][(tn & 1) * 2]);
                }
            }
        }

        __syncthreads();
        if (t + 2 < total)
            att_cp_tile(sb + ((t & 1) ? ATT_B1 : ATT_B0), tile_src(t + 2), tid);
        cp_commit();
    }

    // ---- output: stage (co * inv) into S region, then coalesced stores ----
    const float inv0 = invs[warp * 16 + grp];
    const float inv1 = invs[warp * 16 + grp + 8];
    __half* st = (__half*)(sm + ATT_SOFF);    // 64 x 72 halfs
#pragma unroll
    for (int tn = 0; tn < 8; tn++) {
#pragma unroll
        for (int hf = 0; hf < 2; hf++) {
            const int row = warp * 16 + grp + hf * 8;
            const int col = tn * 8 + qd * 2;
            const float inv = hf ? inv1 : inv0;
            __half2 h = __floats2half2_rn(co[tn][hf * 2 + 0] * inv,
                                          co[tn][hf * 2 + 1] * inv);
            *(__half2*)(st + row * 72 + col) = h;
        }
    }
    __syncthreads();
    {
        const int row = tid >> 1, seg = tid & 1;
        const int token = qtok0 + row;
        if (token < NREAL) {
            const int b_ = bh >> 4, h_ = bh & 15;
            const int m = b_ * NREAL + token;
            __half* dstp = g_oh + (size_t)m * DIMn + h_ * 64 + seg * 32;
            const __half* srcp = st + row * 72 + seg * 32;
#pragma unroll
            for (int i = 0; i < 4; i++)
                *(uint4*)(dstp + i * 8) = *(const uint4*)(srcp + i * 8);
        }
    }
}

// ---------------------------------------------------------------------------
// Launch
// ---------------------------------------------------------------------------
extern "C" void kernel_launch(void* const* d_in, const int* in_sizes, int n_in,
                              void* d_out, int out_size)
{
    (void)in_sizes; (void)n_in; (void)out_size;
    const float* x     = (const float*)d_in[0];
    const float* w_qkv = (const float*)d_in[1];
    const float* w_out = (const float*)d_in[2];
    const float* b_out = (const float*)d_in[3];
    float* out = (float*)d_out;

    cudaFuncSetAttribute(attn_fused_kernel,
                         cudaFuncAttributeMaxDynamicSharedMemorySize, ATT_SMEM);
    cudaFuncSetAttribute(hgemm_kernel<0>,
                         cudaFuncAttributeMaxDynamicSharedMemorySize, HG_SMEM);
    cudaFuncSetAttribute(hgemm_kernel<1>,
                         cudaFuncAttributeMaxDynamicSharedMemorySize, HG_SMEM);

    void* p_xh;    cudaGetSymbolAddress(&p_xh, g_xh);
    void* p_wqkv;  cudaGetSymbolAddress(&p_wqkv, g_wqkvh);
    void* p_wout;  cudaGetSymbolAddress(&p_wout, g_wouth);
    void* p_oh;    cudaGetSymbolAddress(&p_oh, g_oh);

    // 0) fp32 -> fp16 conversions (single merged kernel)
    cvt_all_kernel<<<(CVT_TOT + 255) / 256, 256>>>(x, w_qkv, w_out);

    // 1) QKV projection (fp16 tensor cores) into fp16 head-layout scratch
    hgemm_kernel<0><<<dim3(24, 160), 256, HG_SMEM>>>(
        (const __half*)p_xh, (const __half*)p_wqkv, nullptr, nullptr, MQKV);

    // 2) fused text + axial image attention (image blocks first: LPT order)
    attn_fused_kernel<<<dim3(20, 256), 128, ATT_SMEM>>>();

    // 3) output projection + bias (fp16 tensor cores)
    hgemm_kernel<1><<<dim3(8, 160), 256, HG_SMEM>>>(
        (const __half*)p_oh, (const __half*)p_wout, b_out, out, MOUT);
}

// round 14
// speedup vs baseline: 1.0265x; 1.0022x over previous
#include <cuda_runtime.h>
#include <cuda_fp16.h>
#include <float.h>

// ---------------------------------------------------------------------------
// Problem constants
// ---------------------------------------------------------------------------
#define Bn     16
#define Hn     16
#define DHn    64
#define NTOK   1280          // padded sequence (SEQ_LEN + 1)
#define NREAL  1279          // real tokens
#define DIMn   1024
#define TXT    256           // text length
#define BH     256           // Bn * Hn
#define HD     (NTOK * DHn)  // 81920 halfs per (b,h) plane
#define MQKV   (Bn * NTOK)   // 20480
#define MOUT   (Bn * NREAL)  // 20464
#define QSCALE 0.125f        // DH^-0.5

// ---------------------------------------------------------------------------
// Scratch (device globals: allocation-free)
// ---------------------------------------------------------------------------
__device__ __half g_qh[(size_t)BH * HD];
__device__ __half g_kh[(size_t)BH * HD];
__device__ __half g_vh[(size_t)BH * HD];
__device__ __half g_xh[(size_t)MQKV * DIMn];     // padded x in fp16
__device__ __half g_wqkvh[3 * DIMn * DIMn];      // w_qkv fp16
__device__ __half g_wouth[DIMn * DIMn];          // w_out fp16
__device__ __half g_oh[(size_t)MOUT * DIMn];     // attn out, de-interleaved fp16

// ---------------------------------------------------------------------------
// MMA / ldmatrix helpers
// ---------------------------------------------------------------------------
__device__ __forceinline__ void mma_f16(float c[4], const unsigned a[4],
                                        const unsigned b[2]) {
    asm volatile(
        "mma.sync.aligned.m16n8k16.row.col.f32.f16.f16.f32 "
        "{%0,%1,%2,%3}, {%4,%5,%6,%7}, {%8,%9}, {%0,%1,%2,%3};\n"
        : "+f"(c[0]), "+f"(c[1]), "+f"(c[2]), "+f"(c[3])
        : "r"(a[0]), "r"(a[1]), "r"(a[2]), "r"(a[3]), "r"(b[0]), "r"(b[1]));
}
__device__ __forceinline__ void ldsm4(unsigned& r0, unsigned& r1,
                                      unsigned& r2, unsigned& r3, unsigned addr) {
    asm volatile("ldmatrix.sync.aligned.m8n8.x4.shared.b16 {%0,%1,%2,%3}, [%4];\n"
                 : "=r"(r0), "=r"(r1), "=r"(r2), "=r"(r3) : "r"(addr));
}
__device__ __forceinline__ void ldsm4t(unsigned& r0, unsigned& r1,
                                       unsigned& r2, unsigned& r3, unsigned addr) {
    asm volatile("ldmatrix.sync.aligned.m8n8.x4.trans.shared.b16 {%0,%1,%2,%3}, [%4];\n"
                 : "=r"(r0), "=r"(r1), "=r"(r2), "=r"(r3) : "r"(addr));
}

// Attention/GEMM tiles: 128B rows (64 halfs), chunk c (0..7)
__device__ __forceinline__ unsigned off16(int row, int c) {
    return (unsigned)(row * 128 + ((c ^ (row & 7)) << 4));
}
// Score matrix S: 640B rows (320 halfs), chunk swizzle within 8-chunk groups
__device__ __forceinline__ unsigned sidx16(int row, int c) {
    int cc = (c & ~7) | ((c & 7) ^ (row & 7));
    return (unsigned)(row * 640 + (cc << 4));
}
__device__ __forceinline__ char* sptr(char* base, int row, int col) {
    return base + sidx16(row, col >> 3) + (col & 7) * 2;
}

__device__ __forceinline__ void cp16(unsigned dst, const void* src, bool v) {
    int sz = v ? 16 : 0;
    asm volatile("cp.async.cg.shared.global [%0], [%1], 16, %2;\n"
                 :: "r"(dst), "l"(src), "r"(sz) : "memory");
}
__device__ __forceinline__ void cp_commit() {
    asm volatile("cp.async.commit_group;\n" ::: "memory");
}
__device__ __forceinline__ void cp_wait1() {
    asm volatile("cp.async.wait_group 1;\n" ::: "memory");
}
__device__ __forceinline__ void cp_wait2() {
    asm volatile("cp.async.wait_group 2;\n" ::: "memory");
}

// ---------------------------------------------------------------------------
// fp16 HGEMM (exact R11/R13 version; PROTECTED — measured best).
// 128x128 CTA tile, BK=64 per sync, 3-stage cp.async pipeline
// (96KB dyn smem, 2 CTAs/SM). Smem-staged coalesced epilogues.
// EPI=0: fp16 to g_qh/g_kh/g_vh head layout. EPI=1: fp32 out + bias.
// ---------------------------------------------------------------------------
#define HG_STG  32768
#define HG_SMEM (3 * HG_STG)   // 98304

template <int EPI>
__global__ __launch_bounds__(256, 2) void hgemm_kernel(
    const __half* __restrict__ A, const __half* __restrict__ B,
    const float* __restrict__ bias, float* __restrict__ out, int Mv)
{
    extern __shared__ __align__(16) __half gsm[];
    const unsigned smbase = (unsigned)__cvta_generic_to_shared(gsm);

    const int tid = threadIdx.x;
    const int m0 = blockIdx.y * 128;
    const int n0 = blockIdx.x * 128;

    auto load_stage = [&](int s, int kc) {
        const unsigned sa = smbase + s * HG_STG;
        const int kofs = kc * 64;
#pragma unroll
        for (int r = 0; r < 4; r++) {
            const int id = tid + 256 * r;
            const int row = id >> 3, c = id & 7;
            cp16(sa + off16(row, c),
                 A + (size_t)(m0 + row) * DIMn + kofs + c * 8, (m0 + row) < Mv);
        }
#pragma unroll
        for (int r = 0; r < 4; r++) {
            const int id = tid + 256 * r;
            const int row = id >> 3, c = id & 7;
            cp16(sa + 16384 + off16(row, c),
                 B + (size_t)(n0 + row) * DIMn + kofs + c * 8, true);
        }
    };

    const int lane = tid & 31, warp = tid >> 5;
    const int wM = warp >> 1, wN = warp & 1;         // 4 x 2 warps, 32x64 tile
    const int aRow = wM * 32 + (lane & 15);
    const int aC   = lane >> 4;
    const int bRow = wN * 64 + (lane & 7) + ((lane >> 4) & 1) * 8;
    const int bC   = (lane >> 3) & 1;

    float c[2][8][4];
#pragma unroll
    for (int tm = 0; tm < 2; tm++)
#pragma unroll
        for (int tn = 0; tn < 8; tn++)
#pragma unroll
            for (int i = 0; i < 4; i++) c[tm][tn][i] = 0.f;

    load_stage(0, 0); cp_commit();
    load_stage(1, 1); cp_commit();

#pragma unroll 1
    for (int it = 0; it < 16; it++) {
        cp_wait1();
        __syncthreads();
        const int s = it - (it / 3) * 3;
        const unsigned sa = smbase + s * HG_STG;
        const unsigned sbB = sa + 16384;

#pragma unroll
        for (int k16 = 0; k16 < 4; k16++) {
            unsigned a[2][4], b[4][4];
#pragma unroll
            for (int tm = 0; tm < 2; tm++)
                ldsm4(a[tm][0], a[tm][1], a[tm][2], a[tm][3],
                      sa + off16(aRow + tm * 16, k16 * 2 + aC));
#pragma unroll
            for (int p = 0; p < 4; p++)
                ldsm4(b[p][0], b[p][1], b[p][2], b[p][3],
                      sbB + off16(bRow + p * 16, k16 * 2 + bC));
#pragma unroll
            for (int tm = 0; tm < 2; tm++)
#pragma unroll
                for (int tn = 0; tn < 8; tn++)
                    mma_f16(c[tm][tn], a[tm], &b[tn >> 1][(tn & 1) * 2]);
            if (k16 == 0 && it + 2 < 16) load_stage((it + 2) % 3, it + 2);
        }
        cp_commit();     // one group per iteration (may be empty near tail)
    }

    const int grp = lane >> 2, qd = lane & 3;
    __syncthreads();     // pipeline done; smem becomes epilogue staging

    if (EPI == 0) {
        const int which = n0 >> 10;
        __half* dst = (which == 0) ? g_qh : ((which == 1) ? g_kh : g_vh);
        const float sc = (which == 0) ? QSCALE : 1.0f;
        __half* st = gsm;                 // 128 x 136 halfs
#pragma unroll
        for (int tm = 0; tm < 2; tm++)
#pragma unroll
            for (int hf = 0; hf < 2; hf++) {
                const int row = wM * 32 + tm * 16 + grp + hf * 8;
#pragma unroll
                for (int tn = 0; tn < 8; tn++) {
                    const int col = wN * 64 + tn * 8 + qd * 2;
                    __half2 hv = __floats2half2_rn(c[tm][tn][hf * 2 + 0] * sc,
                                                   c[tm][tn][hf * 2 + 1] * sc);
                    *(__half2*)(st + row * 136 + col) = hv;
                }
            }
        __syncthreads();
        const int r = tid >> 1, seg = tid & 1;
        const int mrow = m0 + r;
        if (mrow < Mv) {
            const int gcol = n0 + seg * 64;
            const int h = (gcol & 1023) >> 6;
            const int b_ = mrow / NTOK;
            const int n_ = mrow - b_ * NTOK;
            __half* base = dst + ((size_t)(b_ * Hn + h) * NTOK + n_) * DHn;
            const __half* src = st + r * 136 + seg * 64;
#pragma unroll
            for (int i = 0; i < 8; i++)
                *(uint4*)(base + i * 8) = *(const uint4*)(src + i * 8);
        }
    } else {
        float* st = (float*)gsm;          // 128 x 136 floats
#pragma unroll
        for (int tm = 0; tm < 2; tm++)
#pragma unroll
            for (int hf = 0; hf < 2; hf++) {
                const int row = wM * 32 + tm * 16 + grp + hf * 8;
#pragma unroll
                for (int tn = 0; tn < 8; tn++) {
                    const int col = wN * 64 + tn * 8 + qd * 2;
                    float2 v = make_float2(c[tm][tn][hf * 2 + 0],
                                           c[tm][tn][hf * 2 + 1]);
                    *(float2*)(st + row * 136 + col) = v;
                }
            }
        __syncthreads();
        const int r = tid >> 1, seg = tid & 1;
        const int mrow = m0 + r;
        if (mrow < Mv) {
            const float* src = st + r * 136 + seg * 64;
            const float* bsrc = bias + n0 + seg * 64;
            float* dstp = out + (size_t)mrow * DIMn + n0 + seg * 64;
#pragma unroll
            for (int i = 0; i < 16; i++) {
                float4 v = *(const float4*)(src + i * 4);
                float4 bb = *(const float4*)(bsrc + i * 4);
                v.x += bb.x; v.y += bb.y; v.z += bb.z; v.w += bb.w;
                *(float4*)(dstp + i * 4) = v;
            }
        }
    }
}

// ---------------------------------------------------------------------------
// cvt v2: one block per padded x row (index math once per block), then
// linear blocks for the two weight matrices. Fully coalesced float4 streams.
// Grid: 20480 x-row blocks + 4096 weight blocks = 24576 blocks x 256 thr.
// ---------------------------------------------------------------------------
#define CVT_XBLK  MQKV                     // 20480
#define CVT_WBLK  (4 * DIMn * DIMn / 1024) // 4096
#define CVT_BLKS  (CVT_XBLK + CVT_WBLK)
#define WQ_ELEMS  (3 * DIMn * DIMn)

__global__ __launch_bounds__(256) void cvt_all_kernel(
    const float* __restrict__ x, const float* __restrict__ wqkv,
    const float* __restrict__ wout)
{
    const int tid = threadIdx.x;
    if (blockIdx.x < CVT_XBLK) {
        const int row = blockIdx.x;
        const int b = row / NTOK;
        const int n = row - b * NTOK;
        const int col = tid * 4;
        float4 v = make_float4(0.f, 0.f, 0.f, 0.f);
        if (n < NREAL)
            v = *(const float4*)(x + ((size_t)b * NREAL + n) * DIMn + col);
        __half2 h0 = __floats2half2_rn(v.x, v.y);
        __half2 h1 = __floats2half2_rn(v.z, v.w);
        uint2 u;
        u.x = *(unsigned*)&h0;
        u.y = *(unsigned*)&h1;
        *(uint2*)(g_xh + (size_t)row * DIMn + col) = u;
    } else {
        const size_t e = ((size_t)(blockIdx.x - CVT_XBLK) * 256 + tid) * 4;
        float4 v;
        __half* dst;
        size_t o;
        if (e < WQ_ELEMS) {
            v = *(const float4*)(wqkv + e);
            dst = g_wqkvh; o = e;
        } else {
            o = e - WQ_ELEMS;
            v = *(const float4*)(wout + o);
            dst = g_wouth;
        }
        __half2 h0 = __floats2half2_rn(v.x, v.y);
        __half2 h1 = __floats2half2_rn(v.z, v.w);
        uint2 u;
        u.x = *(unsigned*)&h0;
        u.y = *(unsigned*)&h1;
        *(uint2*)(dst + o) = u;
    }
}

// ---------------------------------------------------------------------------
// Fused tensor-core attention: 3-buffer cp.async ring (prefetch distance 3),
// vectorized softmax, smem-staged coalesced output, LPT block order.
// smem: Q[64][64] @0, KV bufs @8192/@16384/@24576, S[64][320] @32768,
//       inv[64] @73728. Total 73984 B -> still 3 CTAs/SM (limit 77824).
// ---------------------------------------------------------------------------
#define ATT_QOFF 0
#define ATT_BUF0 8192
#define ATT_SOFF 32768
#define ATT_IOFF 73728
#define ATT_SMEM 73984

__device__ __forceinline__ void att_cp_tile(unsigned dstbase, const __half* g,
                                            int tid) {
#pragma unroll
    for (int r = 0; r < 4; r++) {
        int id = tid + 128 * r;
        int row = id >> 3, c = id & 7;
        cp16(dstbase + off16(row, c), g + row * 64 + c * 8, true);
    }
}

__global__ __launch_bounds__(128) void attn_fused_kernel()
{
    extern __shared__ char sm[];
    const unsigned sb = (unsigned)__cvta_generic_to_shared(sm);
    float* invs = (float*)(sm + ATT_IOFF);

    const int bh = blockIdx.y;
    const int bx = blockIdx.x;
    const bool isText = (bx >= 16);      // LPT: image blocks first
    const int tid = threadIdx.x, lane = tid & 31, warp = tid >> 5;
    const int grp = lane >> 2, qd = lane & 3;

    const int tIdx = bx - 16;
    const int qtok0 = isText ? tIdx * 64 : TXT + bx * 64;

    const __half* qg = g_qh + (size_t)bh * HD + (size_t)qtok0 * DHn;
    const __half* kg = g_kh + (size_t)bh * HD;
    const __half* vg = g_vh + (size_t)bh * HD;

    const int nK = isText ? (tIdx + 1) : 5;
    const int total = 2 * nK;
    const int ncols = isText ? (qtok0 + 64) : (TXT + 32);

    auto tile_src = [&](int t) -> const __half* {
        if (t < nK) {
            if (isText || t < 4) return kg + (size_t)t * 64 * DHn;
            return kg + (size_t)qtok0 * DHn;
        }
        int v = t - nK;
        if (isText || v < 4) return vg + (size_t)v * 64 * DHn;
        return vg + (size_t)qtok0 * DHn;
    };
    auto bufoff = [&](int t) -> unsigned {
        return ATT_BUF0 + (unsigned)(t % 3) * 8192;
    };

    // prologue: Q + tile0 (group0), tile1 (group1), tile2 (group2)
    att_cp_tile(sb + ATT_QOFF, qg, tid);
    att_cp_tile(sb + bufoff(0), tile_src(0), tid);
    cp_commit();
    att_cp_tile(sb + bufoff(1), tile_src(1), tid);
    cp_commit();
    if (total > 2) att_cp_tile(sb + bufoff(2), tile_src(2), tid);
    cp_commit();

    const int aRow = warp * 16 + (lane & 15);
    const int aC   = lane >> 4;
    const int bRow = (lane & 7) + ((lane >> 4) & 1) * 8;
    const int bC   = (lane >> 3) & 1;
    const int kb   = (warp >> 1) * 32;

    float co[8][4];
#pragma unroll
    for (int tn = 0; tn < 8; tn++)
#pragma unroll
        for (int i = 0; i < 4; i++) co[tn][i] = 0.f;

#pragma unroll 1
    for (int t = 0; t < total; t++) {
        cp_wait2();
        __syncthreads();

        if (t == nK) {
            // ---- vectorized softmax: 2 threads/row, uint4 chunks ----
            const int row = tid >> 1, hv = tid & 1;
            const int nch = ncols >> 4;
            const int ch0 = hv * nch;
            char* srow = sm + ATT_SOFF;
            float mx = -FLT_MAX;
#pragma unroll 2
            for (int ch = ch0; ch < ch0 + nch; ch++) {
                uint4 v = *(uint4*)(srow + sidx16(row, ch));
                const __half2* hp = (const __half2*)&v;
#pragma unroll
                for (int i = 0; i < 4; i++) {
                    float2 f = __half22float2(hp[i]);
                    mx = fmaxf(mx, fmaxf(f.x, f.y));
                }
            }
            mx = fmaxf(mx, __shfl_xor_sync(0xffffffffu, mx, 1));
            float sum = 0.f;
#pragma unroll 2
            for (int ch = ch0; ch < ch0 + nch; ch++) {
                char* p = srow + sidx16(row, ch);
                uint4 v = *(uint4*)p;
                __half2* hp = (__half2*)&v;
#pragma unroll
                for (int i = 0; i < 4; i++) {
                    float2 f = __half22float2(hp[i]);
                    f.x = __expf(f.x - mx);
                    f.y = __expf(f.y - mx);
                    sum += f.x + f.y;
                    hp[i] = __floats2half2_rn(f.x, f.y);
                }
                *(uint4*)p = v;
            }
            sum += __shfl_xor_sync(0xffffffffu, sum, 1);
            if (hv == 0) invs[row] = 1.f / sum;
            __syncthreads();
        }

        const unsigned kvb = sb + bufoff(t);

        if (t < nK) {
            const bool imgTile = (!isText) && (t == 4);
            if (!imgTile) {
                const int j0 = t * 64;
                float cs[8][4];
#pragma unroll
                for (int tn = 0; tn < 8; tn++)
#pragma unroll
                    for (int i = 0; i < 4; i++) cs[tn][i] = 0.f;
#pragma unroll
                for (int k16 = 0; k16 < 4; k16++) {
                    unsigned a[4], b[4][4];
                    ldsm4(a[0], a[1], a[2], a[3],
                          sb + ATT_QOFF + off16(aRow, k16 * 2 + aC));
#pragma unroll
                    for (int p = 0; p < 4; p++)
                        ldsm4(b[p][0], b[p][1], b[p][2], b[p][3],
                              kvb + off16(p * 16 + bRow, k16 * 2 + bC));
#pragma unroll
                    for (int tn = 0; tn < 8; tn++)
                        mma_f16(cs[tn], a, &b[tn >> 1][(tn & 1) * 2]);
                }
                const bool diag = isText && (t == nK - 1);
#pragma unroll
                for (int tn = 0; tn < 8; tn++) {
#pragma unroll
                    for (int hf = 0; hf < 2; hf++) {
                        const int row = warp * 16 + grp + hf * 8;
                        const int col = j0 + tn * 8 + qd * 2;
                        float v0 = cs[tn][hf * 2 + 0];
                        float v1 = cs[tn][hf * 2 + 1];
                        if (diag) {
                            const int qglob = qtok0 + row;
                            if (col > qglob)     v0 = -1e30f;
                            if (col + 1 > qglob) v1 = -1e30f;
                        }
                        __half2 h = __floats2half2_rn(v0, v1);
                        *(unsigned*)sptr(sm + ATT_SOFF, row, col) = *(unsigned*)&h;
                    }
                }
            } else {
                float cs[4][4];
#pragma unroll
                for (int tn = 0; tn < 4; tn++)
#pragma unroll
                    for (int i = 0; i < 4; i++) cs[tn][i] = 0.f;
#pragma unroll
                for (int k16 = 0; k16 < 4; k16++) {
                    unsigned a[4], b[2][4];
                    ldsm4(a[0], a[1], a[2], a[3],
                          sb + ATT_QOFF + off16(aRow, k16 * 2 + aC));
#pragma unroll
                    for (int p = 0; p < 2; p++)
                        ldsm4(b[p][0], b[p][1], b[p][2], b[p][3],
                              kvb + off16(kb + p * 16 + bRow, k16 * 2 + bC));
#pragma unroll
                    for (int tn = 0; tn < 4; tn++)
                        mma_f16(cs[tn], a, &b[tn >> 1][(tn & 1) * 2]);
                }
#pragma unroll
                for (int tn = 0; tn < 4; tn++) {
#pragma unroll
                    for (int hf = 0; hf < 2; hf++) {
                        const int row = warp * 16 + grp + hf * 8;
                        const int qlocal = row & 31;
                        const int j = tn * 8 + qd * 2;
                        float v0 = (j     <= qlocal) ? cs[tn][hf * 2 + 0] : -1e30f;
                        float v1 = (j + 1 <= qlocal) ? cs[tn][hf * 2 + 1] : -1e30f;
                        __half2 h = __floats2half2_rn(v0, v1);
                        *(unsigned*)sptr(sm + ATT_SOFF, row, TXT + j) = *(unsigned*)&h;
                    }
                }
            }
        } else {
            const int v = t - nK;
            const bool imgTile = (!isText) && (v == 4);
            if (!imgTile) {
                const int j0 = v * 64;
#pragma unroll
                for (int k16 = 0; k16 < 4; k16++) {
                    unsigned a[4], b[4][4];
                    ldsm4(a[0], a[1], a[2], a[3],
                          sb + ATT_SOFF + sidx16(aRow, (j0 >> 3) + k16 * 2 + aC));
#pragma unroll
                    for (int n16 = 0; n16 < 4; n16++)
                        ldsm4t(b[n16][0], b[n16][1], b[n16][2], b[n16][3],
                               kvb + off16(k16 * 16 + (lane & 15),
                                           n16 * 2 + (lane >> 4)));
#pragma unroll
                    for (int tn = 0; tn < 8; tn++)
                        mma_f16(co[tn], a, &b[tn >> 1][(tn & 1) * 2]);
                }
            } else {
#pragma unroll
                for (int k16 = 0; k16 < 2; k16++) {
                    unsigned a[4], b[4][4];
                    ldsm4(a[0], a[1], a[2], a[3],
                          sb + ATT_SOFF + sidx16(aRow, (TXT >> 3) + k16 * 2 + aC));
#pragma unroll
                    for (int n16 = 0; n16 < 4; n16++)
                        ldsm4t(b[n16][0], b[n16][1], b[n16][2], b[n16][3],
                               kvb + off16(kb + k16 * 16 + (lane & 15),
                                           n16 * 2 + (lane >> 4)));
#pragma unroll
                    for (int tn = 0; tn < 8; tn++)
                        mma_f16(co[tn], a, &b[tn >> 1][(tn & 1) * 2]);
                }
            }
        }

        __syncthreads();
        if (t + 3 < total)
            att_cp_tile(sb + bufoff(t), tile_src(t + 3), tid);
        cp_commit();
    }

    // ---- output: stage (co * inv) into S region, then coalesced stores ----
    const float inv0 = invs[warp * 16 + grp];
    const float inv1 = invs[warp * 16 + grp + 8];
    __half* st = (__half*)(sm + ATT_SOFF);    // 64 x 72 halfs
#pragma unroll
    for (int tn = 0; tn < 8; tn++) {
#pragma unroll
        for (int hf = 0; hf < 2; hf++) {
            const int row = warp * 16 + grp + hf * 8;
            const int col = tn * 8 + qd * 2;
            const float inv = hf ? inv1 : inv0;
            __half2 h = __floats2half2_rn(co[tn][hf * 2 + 0] * inv,
                                          co[tn][hf * 2 + 1] * inv);
            *(__half2*)(st + row * 72 + col) = h;
        }
    }
    __syncthreads();
    {
        const int row = tid >> 1, seg = tid & 1;
        const int token = qtok0 + row;
        if (token < NREAL) {
            const int b_ = bh >> 4, h_ = bh & 15;
            const int m = b_ * NREAL + token;
            __half* dstp = g_oh + (size_t)m * DIMn + h_ * 64 + seg * 32;
            const __half* srcp = st + row * 72 + seg * 32;
#pragma unroll
            for (int i = 0; i < 4; i++)
                *(uint4*)(dstp + i * 8) = *(const uint4*)(srcp + i * 8);
        }
    }
}

// ---------------------------------------------------------------------------
// Launch
// ---------------------------------------------------------------------------
extern "C" void kernel_launch(void* const* d_in, const int* in_sizes, int n_in,
                              void* d_out, int out_size)
{
    (void)in_sizes; (void)n_in; (void)out_size;
    const float* x     = (const float*)d_in[0];
    const float* w_qkv = (const float*)d_in[1];
    const float* w_out = (const float*)d_in[2];
    const float* b_out = (const float*)d_in[3];
    float* out = (float*)d_out;

    cudaFuncSetAttribute(attn_fused_kernel,
                         cudaFuncAttributeMaxDynamicSharedMemorySize, ATT_SMEM);
    cudaFuncSetAttribute(hgemm_kernel<0>,
                         cudaFuncAttributeMaxDynamicSharedMemorySize, HG_SMEM);
    cudaFuncSetAttribute(hgemm_kernel<1>,
                         cudaFuncAttributeMaxDynamicSharedMemorySize, HG_SMEM);

    void* p_xh;    cudaGetSymbolAddress(&p_xh, g_xh);
    void* p_wqkv;  cudaGetSymbolAddress(&p_wqkv, g_wqkvh);
    void* p_wout;  cudaGetSymbolAddress(&p_wout, g_wouth);
    void* p_oh;    cudaGetSymbolAddress(&p_oh, g_oh);

    // 0) fp32 -> fp16 conversions (row-per-block x + linear weights)
    cvt_all_kernel<<<CVT_BLKS, 256>>>(x, w_qkv, w_out);

    // 1) QKV projection (fp16 tensor cores) into fp16 head-layout scratch
    hgemm_kernel<0><<<dim3(24, 160), 256, HG_SMEM>>>(
        (const __half*)p_xh, (const __half*)p_wqkv, nullptr, nullptr, MQKV);

    // 2) fused text + axial image attention (3-buffer ring, LPT order)
    attn_fused_kernel<<<dim3(20, 256), 128, ATT_SMEM>>>();

    // 3) output projection + bias (fp16 tensor cores)
    hgemm_kernel<1><<<dim3(8, 160), 256, HG_SMEM>>>(
        (const __half*)p_oh, (const __half*)p_wout, b_out, out, MOUT);
}

// round 15
// speedup vs baseline: 1.0703x; 1.0427x over previous
#include <cuda_runtime.h>
#include <cuda_fp16.h>
#include <float.h>

// ---------------------------------------------------------------------------
// Problem constants
// ---------------------------------------------------------------------------
#define Bn     16
#define Hn     16
#define DHn    64
#define NTOK   1280          // padded sequence (SEQ_LEN + 1)
#define NREAL  1279          // real tokens
#define DIMn   1024
#define TXT    256           // text length
#define BH     256           // Bn * Hn
#define HD     (NTOK * DHn)  // 81920 halfs per (b,h) plane
#define MQKV   (Bn * NTOK)   // 20480
#define MOUT   (Bn * NREAL)  // 20464
#define QSCALE 0.125f        // DH^-0.5

// ---------------------------------------------------------------------------
// Scratch (device globals: allocation-free)
// ---------------------------------------------------------------------------
__device__ __half g_qh[(size_t)BH * HD];
__device__ __half g_kh[(size_t)BH * HD];
__device__ __half g_vh[(size_t)BH * HD];
__device__ __half g_xh[(size_t)MQKV * DIMn];     // padded x in fp16
__device__ __half g_wqkvh[3 * DIMn * DIMn];      // w_qkv fp16
__device__ __half g_wouth[DIMn * DIMn];          // w_out fp16
__device__ __half g_oh[(size_t)MOUT * DIMn];     // attn out, de-interleaved fp16

// ---------------------------------------------------------------------------
// MMA / ldmatrix helpers
// ---------------------------------------------------------------------------
__device__ __forceinline__ void mma_f16(float c[4], const unsigned a[4],
                                        const unsigned b[2]) {
    asm volatile(
        "mma.sync.aligned.m16n8k16.row.col.f32.f16.f16.f32 "
        "{%0,%1,%2,%3}, {%4,%5,%6,%7}, {%8,%9}, {%0,%1,%2,%3};\n"
        : "+f"(c[0]), "+f"(c[1]), "+f"(c[2]), "+f"(c[3])
        : "r"(a[0]), "r"(a[1]), "r"(a[2]), "r"(a[3]), "r"(b[0]), "r"(b[1]));
}
__device__ __forceinline__ void ldsm4(unsigned& r0, unsigned& r1,
                                      unsigned& r2, unsigned& r3, unsigned addr) {
    asm volatile("ldmatrix.sync.aligned.m8n8.x4.shared.b16 {%0,%1,%2,%3}, [%4];\n"
                 : "=r"(r0), "=r"(r1), "=r"(r2), "=r"(r3) : "r"(addr));
}
__device__ __forceinline__ void ldsm4t(unsigned& r0, unsigned& r1,
                                       unsigned& r2, unsigned& r3, unsigned addr) {
    asm volatile("ldmatrix.sync.aligned.m8n8.x4.trans.shared.b16 {%0,%1,%2,%3}, [%4];\n"
                 : "=r"(r0), "=r"(r1), "=r"(r2), "=r"(r3) : "r"(addr));
}

// Attention/GEMM tiles: 128B rows (64 halfs), chunk c (0..7)
__device__ __forceinline__ unsigned off16(int row, int c) {
    return (unsigned)(row * 128 + ((c ^ (row & 7)) << 4));
}
// Score matrix S: 640B rows (320 halfs), chunk swizzle within 8-chunk groups
__device__ __forceinline__ unsigned sidx16(int row, int c) {
    int cc = (c & ~7) | ((c & 7) ^ (row & 7));
    return (unsigned)(row * 640 + (cc << 4));
}
__device__ __forceinline__ char* sptr(char* base, int row, int col) {
    return base + sidx16(row, col >> 3) + (col & 7) * 2;
}

__device__ __forceinline__ void cp16(unsigned dst, const void* src, bool v) {
    int sz = v ? 16 : 0;
    asm volatile("cp.async.cg.shared.global [%0], [%1], 16, %2;\n"
                 :: "r"(dst), "l"(src), "r"(sz) : "memory");
}
__device__ __forceinline__ void cp_commit() {
    asm volatile("cp.async.commit_group;\n" ::: "memory");
}
__device__ __forceinline__ void cp_wait1() {
    asm volatile("cp.async.wait_group 1;\n" ::: "memory");
}
__device__ __forceinline__ void cp_wait2() {
    asm volatile("cp.async.wait_group 2;\n" ::: "memory");
}

// ---------------------------------------------------------------------------
// fp16 HGEMM v4: 128x128 CTA tile, BK=64 per sync, 3-stage cp.async pipeline
// (96KB dyn smem). NOW 128 threads = 4 warps of 64x64 warp tiles (2x2):
// fragment smem traffic per FLOP drops 33% (8 ldsm for 2x FLOP vs 6 for 1x),
// relieving the measured crossbar co-bottleneck (L1 63% > tensor 52%).
// 2 CTAs/SM (regs ~190 x 256 thr = 48.6K). Smem-staged coalesced epilogues.
// EPI=0: fp16 to g_qh/g_kh/g_vh head layout. EPI=1: fp32 out + bias.
// ---------------------------------------------------------------------------
#define HG_STG  32768
#define HG_SMEM (3 * HG_STG)   // 98304

template <int EPI>
__global__ __launch_bounds__(128, 2) void hgemm_kernel(
    const __half* __restrict__ A, const __half* __restrict__ B,
    const float* __restrict__ bias, float* __restrict__ out, int Mv)
{
    extern __shared__ __align__(16) __half gsm[];
    const unsigned smbase = (unsigned)__cvta_generic_to_shared(gsm);

    const int tid = threadIdx.x;
    const int m0 = blockIdx.y * 128;
    const int n0 = blockIdx.x * 128;

    auto load_stage = [&](int s, int kc) {
        const unsigned sa = smbase + s * HG_STG;
        const int kofs = kc * 64;
#pragma unroll
        for (int r = 0; r < 8; r++) {
            const int id = tid + 128 * r;
            const int row = id >> 3, c = id & 7;
            cp16(sa + off16(row, c),
                 A + (size_t)(m0 + row) * DIMn + kofs + c * 8, (m0 + row) < Mv);
        }
#pragma unroll
        for (int r = 0; r < 8; r++) {
            const int id = tid + 128 * r;
            const int row = id >> 3, c = id & 7;
            cp16(sa + 16384 + off16(row, c),
                 B + (size_t)(n0 + row) * DIMn + kofs + c * 8, true);
        }
    };

    const int lane = tid & 31, warp = tid >> 5;
    const int wM = warp >> 1, wN = warp & 1;         // 2 x 2 warps, 64x64 tile
    const int aRow = wM * 64 + (lane & 15);
    const int aC   = lane >> 4;
    const int bRow = wN * 64 + (lane & 7) + ((lane >> 4) & 1) * 8;
    const int bC   = (lane >> 3) & 1;

    float c[4][8][4];
#pragma unroll
    for (int tm = 0; tm < 4; tm++)
#pragma unroll
        for (int tn = 0; tn < 8; tn++)
#pragma unroll
            for (int i = 0; i < 4; i++) c[tm][tn][i] = 0.f;

    load_stage(0, 0); cp_commit();
    load_stage(1, 1); cp_commit();

#pragma unroll 1
    for (int it = 0; it < 16; it++) {
        cp_wait1();
        __syncthreads();
        const int s = it - (it / 3) * 3;
        const unsigned sa = smbase + s * HG_STG;
        const unsigned sbB = sa + 16384;

#pragma unroll
        for (int k16 = 0; k16 < 4; k16++) {
            unsigned a[4][4], b[4][4];
#pragma unroll
            for (int tm = 0; tm < 4; tm++)
                ldsm4(a[tm][0], a[tm][1], a[tm][2], a[tm][3],
                      sa + off16(aRow + tm * 16, k16 * 2 + aC));
#pragma unroll
            for (int p = 0; p < 4; p++)
                ldsm4(b[p][0], b[p][1], b[p][2], b[p][3],
                      sbB + off16(bRow + p * 16, k16 * 2 + bC));
#pragma unroll
            for (int tm = 0; tm < 4; tm++)
#pragma unroll
                for (int tn = 0; tn < 8; tn++)
                    mma_f16(c[tm][tn], a[tm], &b[tn >> 1][(tn & 1) * 2]);
            if (k16 == 0 && it + 2 < 16) load_stage((it + 2) % 3, it + 2);
        }
        cp_commit();     // one group per iteration (may be empty near tail)
    }

    const int grp = lane >> 2, qd = lane & 3;
    __syncthreads();     // pipeline done; smem becomes epilogue staging

    if (EPI == 0) {
        const int which = n0 >> 10;      // block-constant (n0 multiple of 128)
        __half* dst = (which == 0) ? g_qh : ((which == 1) ? g_kh : g_vh);
        const float sc = (which == 0) ? QSCALE : 1.0f;
        __half* st = gsm;                 // 128 x 136 halfs
#pragma unroll
        for (int tm = 0; tm < 4; tm++)
#pragma unroll
            for (int hf = 0; hf < 2; hf++) {
                const int row = wM * 64 + tm * 16 + grp + hf * 8;
#pragma unroll
                for (int tn = 0; tn < 8; tn++) {
                    const int col = wN * 64 + tn * 8 + qd * 2;
                    __half2 hv = __floats2half2_rn(c[tm][tn][hf * 2 + 0] * sc,
                                                   c[tm][tn][hf * 2 + 1] * sc);
                    *(__half2*)(st + row * 136 + col) = hv;
                }
            }
        __syncthreads();
        const int r = tid;               // one row per thread
        const int mrow = m0 + r;
        if (mrow < Mv) {
            const int b_ = mrow / NTOK;
            const int n_ = mrow - b_ * NTOK;
#pragma unroll
            for (int seg = 0; seg < 2; seg++) {
                const int gcol = n0 + seg * 64;
                const int h = (gcol & 1023) >> 6;
                __half* base = dst + ((size_t)(b_ * Hn + h) * NTOK + n_) * DHn;
                const __half* src = st + r * 136 + seg * 64;
#pragma unroll
                for (int i = 0; i < 8; i++)
                    *(uint4*)(base + i * 8) = *(const uint4*)(src + i * 8);
            }
        }
    } else {
        float* st = (float*)gsm;          // 128 x 136 floats
#pragma unroll
        for (int tm = 0; tm < 4; tm++)
#pragma unroll
            for (int hf = 0; hf < 2; hf++) {
                const int row = wM * 64 + tm * 16 + grp + hf * 8;
#pragma unroll
                for (int tn = 0; tn < 8; tn++) {
                    const int col = wN * 64 + tn * 8 + qd * 2;
                    float2 v = make_float2(c[tm][tn][hf * 2 + 0],
                                           c[tm][tn][hf * 2 + 1]);
                    *(float2*)(st + row * 136 + col) = v;
                }
            }
        __syncthreads();
        const int r = tid;
        const int mrow = m0 + r;
        if (mrow < Mv) {
            const float* src = st + r * 136;
            const float* bsrc = bias + n0;
            float* dstp = out + (size_t)mrow * DIMn + n0;
#pragma unroll
            for (int i = 0; i < 32; i++) {
                float4 v = *(const float4*)(src + i * 4);
                float4 bb = *(const float4*)(bsrc + i * 4);
                v.x += bb.x; v.y += bb.y; v.z += bb.z; v.w += bb.w;
                *(float4*)(dstp + i * 4) = v;
            }
        }
    }
}

// ---------------------------------------------------------------------------
// cvt v2: one block per padded x row, linear blocks for weights.
// ---------------------------------------------------------------------------
#define CVT_XBLK  MQKV                     // 20480
#define CVT_WBLK  (4 * DIMn * DIMn / 1024) // 4096
#define CVT_BLKS  (CVT_XBLK + CVT_WBLK)
#define WQ_ELEMS  (3 * DIMn * DIMn)

__global__ __launch_bounds__(256) void cvt_all_kernel(
    const float* __restrict__ x, const float* __restrict__ wqkv,
    const float* __restrict__ wout)
{
    const int tid = threadIdx.x;
    if (blockIdx.x < CVT_XBLK) {
        const int row = blockIdx.x;
        const int b = row / NTOK;
        const int n = row - b * NTOK;
        const int col = tid * 4;
        float4 v = make_float4(0.f, 0.f, 0.f, 0.f);
        if (n < NREAL)
            v = *(const float4*)(x + ((size_t)b * NREAL + n) * DIMn + col);
        __half2 h0 = __floats2half2_rn(v.x, v.y);
        __half2 h1 = __floats2half2_rn(v.z, v.w);
        uint2 u;
        u.x = *(unsigned*)&h0;
        u.y = *(unsigned*)&h1;
        *(uint2*)(g_xh + (size_t)row * DIMn + col) = u;
    } else {
        const size_t e = ((size_t)(blockIdx.x - CVT_XBLK) * 256 + tid) * 4;
        float4 v;
        __half* dst;
        size_t o;
        if (e < WQ_ELEMS) {
            v = *(const float4*)(wqkv + e);
            dst = g_wqkvh; o = e;
        } else {
            o = e - WQ_ELEMS;
            v = *(const float4*)(wout + o);
            dst = g_wouth;
        }
        __half2 h0 = __floats2half2_rn(v.x, v.y);
        __half2 h1 = __floats2half2_rn(v.z, v.w);
        uint2 u;
        u.x = *(unsigned*)&h0;
        u.y = *(unsigned*)&h1;
        *(uint2*)(dst + o) = u;
    }
}

// ---------------------------------------------------------------------------
// Fused tensor-core attention (R14: 3-buffer ring, vectorized softmax,
// smem-staged coalesced output, LPT order). PROTECTED.
// ---------------------------------------------------------------------------
#define ATT_QOFF 0
#define ATT_BUF0 8192
#define ATT_SOFF 32768
#define ATT_IOFF 73728
#define ATT_SMEM 73984

__device__ __forceinline__ void att_cp_tile(unsigned dstbase, const __half* g,
                                            int tid) {
#pragma unroll
    for (int r = 0; r < 4; r++) {
        int id = tid + 128 * r;
        int row = id >> 3, c = id & 7;
        cp16(dstbase + off16(row, c), g + row * 64 + c * 8, true);
    }
}

__global__ __launch_bounds__(128) void attn_fused_kernel()
{
    extern __shared__ char sm[];
    const unsigned sb = (unsigned)__cvta_generic_to_shared(sm);
    float* invs = (float*)(sm + ATT_IOFF);

    const int bh = blockIdx.y;
    const int bx = blockIdx.x;
    const bool isText = (bx >= 16);      // LPT: image blocks first
    const int tid = threadIdx.x, lane = tid & 31, warp = tid >> 5;
    const int grp = lane >> 2, qd = lane & 3;

    const int tIdx = bx - 16;
    const int qtok0 = isText ? tIdx * 64 : TXT + bx * 64;

    const __half* qg = g_qh + (size_t)bh * HD + (size_t)qtok0 * DHn;
    const __half* kg = g_kh + (size_t)bh * HD;
    const __half* vg = g_vh + (size_t)bh * HD;

    const int nK = isText ? (tIdx + 1) : 5;
    const int total = 2 * nK;
    const int ncols = isText ? (qtok0 + 64) : (TXT + 32);

    auto tile_src = [&](int t) -> const __half* {
        if (t < nK) {
            if (isText || t < 4) return kg + (size_t)t * 64 * DHn;
            return kg + (size_t)qtok0 * DHn;
        }
        int v = t - nK;
        if (isText || v < 4) return vg + (size_t)v * 64 * DHn;
        return vg + (size_t)qtok0 * DHn;
    };
    auto bufoff = [&](int t) -> unsigned {
        return ATT_BUF0 + (unsigned)(t % 3) * 8192;
    };

    att_cp_tile(sb + ATT_QOFF, qg, tid);
    att_cp_tile(sb + bufoff(0), tile_src(0), tid);
    cp_commit();
    att_cp_tile(sb + bufoff(1), tile_src(1), tid);
    cp_commit();
    if (total > 2) att_cp_tile(sb + bufoff(2), tile_src(2), tid);
    cp_commit();

    const int aRow = warp * 16 + (lane & 15);
    const int aC   = lane >> 4;
    const int bRow = (lane & 7) + ((lane >> 4) & 1) * 8;
    const int bC   = (lane >> 3) & 1;
    const int kb   = (warp >> 1) * 32;

    float co[8][4];
#pragma unroll
    for (int tn = 0; tn < 8; tn++)
#pragma unroll
        for (int i = 0; i < 4; i++) co[tn][i] = 0.f;

#pragma unroll 1
    for (int t = 0; t < total; t++) {
        cp_wait2();
        __syncthreads();

        if (t == nK) {
            const int row = tid >> 1, hv = tid & 1;
            const int nch = ncols >> 4;
            const int ch0 = hv * nch;
            char* srow = sm + ATT_SOFF;
            float mx = -FLT_MAX;
#pragma unroll 2
            for (int ch = ch0; ch < ch0 + nch; ch++) {
                uint4 v = *(uint4*)(srow + sidx16(row, ch));
                const __half2* hp = (const __half2*)&v;
#pragma unroll
                for (int i = 0; i < 4; i++) {
                    float2 f = __half22float2(hp[i]);
                    mx = fmaxf(mx, fmaxf(f.x, f.y));
                }
            }
            mx = fmaxf(mx, __shfl_xor_sync(0xffffffffu, mx, 1));
            float sum = 0.f;
#pragma unroll 2
            for (int ch = ch0; ch < ch0 + nch; ch++) {
                char* p = srow + sidx16(row, ch);
                uint4 v = *(uint4*)p;
                __half2* hp = (__half2*)&v;
#pragma unroll
                for (int i = 0; i < 4; i++) {
                    float2 f = __half22float2(hp[i]);
                    f.x = __expf(f.x - mx);
                    f.y = __expf(f.y - mx);
                    sum += f.x + f.y;
                    hp[i] = __floats2half2_rn(f.x, f.y);
                }
                *(uint4*)p = v;
            }
            sum += __shfl_xor_sync(0xffffffffu, sum, 1);
            if (hv == 0) invs[row] = 1.f / sum;
            __syncthreads();
        }

        const unsigned kvb = sb + bufoff(t);

        if (t < nK) {
            const bool imgTile = (!isText) && (t == 4);
            if (!imgTile) {
                const int j0 = t * 64;
                float cs[8][4];
#pragma unroll
                for (int tn = 0; tn < 8; tn++)
#pragma unroll
                    for (int i = 0; i < 4; i++) cs[tn][i] = 0.f;
#pragma unroll
                for (int k16 = 0; k16 < 4; k16++) {
                    unsigned a[4], b[4][4];
                    ldsm4(a[0], a[1], a[2], a[3],
                          sb + ATT_QOFF + off16(aRow, k16 * 2 + aC));
#pragma unroll
                    for (int p = 0; p < 4; p++)
                        ldsm4(b[p][0], b[p][1], b[p][2], b[p][3],
                              kvb + off16(p * 16 + bRow, k16 * 2 + bC));
#pragma unroll
                    for (int tn = 0; tn < 8; tn++)
                        mma_f16(cs[tn], a, &b[tn >> 1][(tn & 1) * 2]);
                }
                const bool diag = isText && (t == nK - 1);
#pragma unroll
                for (int tn = 0; tn < 8; tn++) {
#pragma unroll
                    for (int hf = 0; hf < 2; hf++) {
                        const int row = warp * 16 + grp + hf * 8;
                        const int col = j0 + tn * 8 + qd * 2;
                        float v0 = cs[tn][hf * 2 + 0];
                        float v1 = cs[tn][hf * 2 + 1];
                        if (diag) {
                            const int qglob = qtok0 + row;
                            if (col > qglob)     v0 = -1e30f;
                            if (col + 1 > qglob) v1 = -1e30f;
                        }
                        __half2 h = __floats2half2_rn(v0, v1);
                        *(unsigned*)sptr(sm + ATT_SOFF, row, col) = *(unsigned*)&h;
                    }
                }
            } else {
                float cs[4][4];
#pragma unroll
                for (int tn = 0; tn < 4; tn++)
#pragma unroll
                    for (int i = 0; i < 4; i++) cs[tn][i] = 0.f;
#pragma unroll
                for (int k16 = 0; k16 < 4; k16++) {
                    unsigned a[4], b[2][4];
                    ldsm4(a[0], a[1], a[2], a[3],
                          sb + ATT_QOFF + off16(aRow, k16 * 2 + aC));
#pragma unroll
                    for (int p = 0; p < 2; p++)
                        ldsm4(b[p][0], b[p][1], b[p][2], b[p][3],
                              kvb + off16(kb + p * 16 + bRow, k16 * 2 + bC));
#pragma unroll
                    for (int tn = 0; tn < 4; tn++)
                        mma_f16(cs[tn], a, &b[tn >> 1][(tn & 1) * 2]);
                }
#pragma unroll
                for (int tn = 0; tn < 4; tn++) {
#pragma unroll
                    for (int hf = 0; hf < 2; hf++) {
                        const int row = warp * 16 + grp + hf * 8;
                        const int qlocal = row & 31;
                        const int j = tn * 8 + qd * 2;
                        float v0 = (j     <= qlocal) ? cs[tn][hf * 2 + 0] : -1e30f;
                        float v1 = (j + 1 <= qlocal) ? cs[tn][hf * 2 + 1] : -1e30f;
                        __half2 h = __floats2half2_rn(v0, v1);
                        *(unsigned*)sptr(sm + ATT_SOFF, row, TXT + j) = *(unsigned*)&h;
                    }
                }
            }
        } else {
            const int v = t - nK;
            const bool imgTile = (!isText) && (v == 4);
            if (!imgTile) {
                const int j0 = v * 64;
#pragma unroll
                for (int k16 = 0; k16 < 4; k16++) {
                    unsigned a[4], b[4][4];
                    ldsm4(a[0], a[1], a[2], a[3],
                          sb + ATT_SOFF + sidx16(aRow, (j0 >> 3) + k16 * 2 + aC));
#pragma unroll
                    for (int n16 = 0; n16 < 4; n16++)
                        ldsm4t(b[n16][0], b[n16][1], b[n16][2], b[n16][3],
                               kvb + off16(k16 * 16 + (lane & 15),
                                           n16 * 2 + (lane >> 4)));
#pragma unroll
                    for (int tn = 0; tn < 8; tn++)
                        mma_f16(co[tn], a, &b[tn >> 1][(tn & 1) * 2]);
                }
            } else {
#pragma unroll
                for (int k16 = 0; k16 < 2; k16++) {
                    unsigned a[4], b[4][4];
                    ldsm4(a[0], a[1], a[2], a[3],
                          sb + ATT_SOFF + sidx16(aRow, (TXT >> 3) + k16 * 2 + aC));
#pragma unroll
                    for (int n16 = 0; n16 < 4; n16++)
                        ldsm4t(b[n16][0], b[n16][1], b[n16][2], b[n16][3],
                               kvb + off16(kb + k16 * 16 + (lane & 15),
                                           n16 * 2 + (lane >> 4)));
#pragma unroll
                    for (int tn = 0; tn < 8; tn++)
                        mma_f16(co[tn], a, &b[tn >> 1][(tn & 1) * 2]);
                }
            }
        }

        __syncthreads();
        if (t + 3 < total)
            att_cp_tile(sb + bufoff(t), tile_src(t + 3), tid);
        cp_commit();
    }

    // ---- output: stage (co * inv) into S region, then coalesced stores ----
    const float inv0 = invs[warp * 16 + grp];
    const float inv1 = invs[warp * 16 + grp + 8];
    __half* st = (__half*)(sm + ATT_SOFF);    // 64 x 72 halfs
#pragma unroll
    for (int tn = 0; tn < 8; tn++) {
#pragma unroll
        for (int hf = 0; hf < 2; hf++) {
            const int row = warp * 16 + grp + hf * 8;
            const int col = tn * 8 + qd * 2;
            const float inv = hf ? inv1 : inv0;
            __half2 h = __floats2half2_rn(co[tn][hf * 2 + 0] * inv,
                                          co[tn][hf * 2 + 1] * inv);
            *(__half2*)(st + row * 72 + col) = h;
        }
    }
    __syncthreads();
    {
        const int row = tid >> 1, seg = tid & 1;
        const int token = qtok0 + row;
        if (token < NREAL) {
            const int b_ = bh >> 4, h_ = bh & 15;
            const int m = b_ * NREAL + token;
            __half* dstp = g_oh + (size_t)m * DIMn + h_ * 64 + seg * 32;
            const __half* srcp = st + row * 72 + seg * 32;
#pragma unroll
            for (int i = 0; i < 4; i++)
                *(uint4*)(dstp + i * 8) = *(const uint4*)(srcp + i * 8);
        }
    }
}

// ---------------------------------------------------------------------------
// Launch
// ---------------------------------------------------------------------------
extern "C" void kernel_launch(void* const* d_in, const int* in_sizes, int n_in,
                              void* d_out, int out_size)
{
    (void)in_sizes; (void)n_in; (void)out_size;
    const float* x     = (const float*)d_in[0];
    const float* w_qkv = (const float*)d_in[1];
    const float* w_out = (const float*)d_in[2];
    const float* b_out = (const float*)d_in[3];
    float* out = (float*)d_out;

    cudaFuncSetAttribute(attn_fused_kernel,
                         cudaFuncAttributeMaxDynamicSharedMemorySize, ATT_SMEM);
    cudaFuncSetAttribute(hgemm_kernel<0>,
                         cudaFuncAttributeMaxDynamicSharedMemorySize, HG_SMEM);
    cudaFuncSetAttribute(hgemm_kernel<1>,
                         cudaFuncAttributeMaxDynamicSharedMemorySize, HG_SMEM);

    void* p_xh;    cudaGetSymbolAddress(&p_xh, g_xh);
    void* p_wqkv;  cudaGetSymbolAddress(&p_wqkv, g_wqkvh);
    void* p_wout;  cudaGetSymbolAddress(&p_wout, g_wouth);
    void* p_oh;    cudaGetSymbolAddress(&p_oh, g_oh);

    // 0) fp32 -> fp16 conversions
    cvt_all_kernel<<<CVT_BLKS, 256>>>(x, w_qkv, w_out);

    // 1) QKV projection (fp16 tensor cores, 128-thread blocks)
    hgemm_kernel<0><<<dim3(24, 160), 128, HG_SMEM>>>(
        (const __half*)p_xh, (const __half*)p_wqkv, nullptr, nullptr, MQKV);

    // 2) fused text + axial image attention
    attn_fused_kernel<<<dim3(20, 256), 128, ATT_SMEM>>>();

    // 3) output projection + bias
    hgemm_kernel<1><<<dim3(8, 160), 128, HG_SMEM>>>(
        (const __half*)p_oh, (const __half*)p_wout, b_out, out, MOUT);
}

// round 16
// speedup vs baseline: 1.1501x; 1.0745x over previous
#include <cuda_runtime.h>
#include <cuda_fp16.h>
#include <float.h>

// ---------------------------------------------------------------------------
// Problem constants
// ---------------------------------------------------------------------------
#define Bn     16
#define Hn     16
#define DHn    64
#define NTOK   1280          // padded sequence (SEQ_LEN + 1)
#define NREAL  1279          // real tokens
#define DIMn   1024
#define TXT    256           // text length
#define BH     256           // Bn * Hn
#define HD     (NTOK * DHn)  // 81920 halfs per (b,h) plane
#define MQKV   (Bn * NTOK)   // 20480
#define MOUT   (Bn * NREAL)  // 20464
#define QSCALE 0.125f        // DH^-0.5

// ---------------------------------------------------------------------------
// Scratch (device globals: allocation-free)
// ---------------------------------------------------------------------------
__device__ __half g_qh[(size_t)BH * HD];
__device__ __half g_kh[(size_t)BH * HD];
__device__ __half g_vh[(size_t)BH * HD];
__device__ __half g_xh[(size_t)MQKV * DIMn];     // padded x in fp16
__device__ __half g_wqkvh[3 * DIMn * DIMn];      // w_qkv fp16
__device__ __half g_wouth[DIMn * DIMn];          // w_out fp16
__device__ __half g_oh[(size_t)MOUT * DIMn];     // attn out, de-interleaved fp16

// ---------------------------------------------------------------------------
// MMA / ldmatrix helpers
// ---------------------------------------------------------------------------
__device__ __forceinline__ void mma_f16(float c[4], const unsigned a[4],
                                        const unsigned b[2]) {
    asm volatile(
        "mma.sync.aligned.m16n8k16.row.col.f32.f16.f16.f32 "
        "{%0,%1,%2,%3}, {%4,%5,%6,%7}, {%8,%9}, {%0,%1,%2,%3};\n"
        : "+f"(c[0]), "+f"(c[1]), "+f"(c[2]), "+f"(c[3])
        : "r"(a[0]), "r"(a[1]), "r"(a[2]), "r"(a[3]), "r"(b[0]), "r"(b[1]));
}
__device__ __forceinline__ void ldsm4(unsigned& r0, unsigned& r1,
                                      unsigned& r2, unsigned& r3, unsigned addr) {
    asm volatile("ldmatrix.sync.aligned.m8n8.x4.shared.b16 {%0,%1,%2,%3}, [%4];\n"
                 : "=r"(r0), "=r"(r1), "=r"(r2), "=r"(r3) : "r"(addr));
}
__device__ __forceinline__ void ldsm4t(unsigned& r0, unsigned& r1,
                                       unsigned& r2, unsigned& r3, unsigned addr) {
    asm volatile("ldmatrix.sync.aligned.m8n8.x4.trans.shared.b16 {%0,%1,%2,%3}, [%4];\n"
                 : "=r"(r0), "=r"(r1), "=r"(r2), "=r"(r3) : "r"(addr));
}

// Tiles: 128B rows (64 halfs), chunk c (0..7)
__device__ __forceinline__ unsigned off16(int row, int c) {
    return (unsigned)(row * 128 + ((c ^ (row & 7)) << 4));
}

__device__ __forceinline__ void cp16(unsigned dst, const void* src, bool v) {
    int sz = v ? 16 : 0;
    asm volatile("cp.async.cg.shared.global [%0], [%1], 16, %2;\n"
                 :: "r"(dst), "l"(src), "r"(sz) : "memory");
}
__device__ __forceinline__ void cp_commit() {
    asm volatile("cp.async.commit_group;\n" ::: "memory");
}
__device__ __forceinline__ void cp_wait1() {
    asm volatile("cp.async.wait_group 1;\n" ::: "memory");
}

__device__ __forceinline__ unsigned packh2(float x, float y) {
    __half2 h = __floats2half2_rn(x, y);
    return *(unsigned*)&h;
}

// ---------------------------------------------------------------------------
// fp16 HGEMM (exact R15 version; PROTECTED — measured best).
// 128x128 CTA tile, BK=64, 3-stage cp.async (96KB), 128 thr = 4 warps 64x64.
// ---------------------------------------------------------------------------
#define HG_STG  32768
#define HG_SMEM (3 * HG_STG)   // 98304

template <int EPI>
__global__ __launch_bounds__(128, 2) void hgemm_kernel(
    const __half* __restrict__ A, const __half* __restrict__ B,
    const float* __restrict__ bias, float* __restrict__ out, int Mv)
{
    extern __shared__ __align__(16) __half gsm[];
    const unsigned smbase = (unsigned)__cvta_generic_to_shared(gsm);

    const int tid = threadIdx.x;
    const int m0 = blockIdx.y * 128;
    const int n0 = blockIdx.x * 128;

    auto load_stage = [&](int s, int kc) {
        const unsigned sa = smbase + s * HG_STG;
        const int kofs = kc * 64;
#pragma unroll
        for (int r = 0; r < 8; r++) {
            const int id = tid + 128 * r;
            const int row = id >> 3, c = id & 7;
            cp16(sa + off16(row, c),
                 A + (size_t)(m0 + row) * DIMn + kofs + c * 8, (m0 + row) < Mv);
        }
#pragma unroll
        for (int r = 0; r < 8; r++) {
            const int id = tid + 128 * r;
            const int row = id >> 3, c = id & 7;
            cp16(sa + 16384 + off16(row, c),
                 B + (size_t)(n0 + row) * DIMn + kofs + c * 8, true);
        }
    };

    const int lane = tid & 31, warp = tid >> 5;
    const int wM = warp >> 1, wN = warp & 1;         // 2 x 2 warps, 64x64 tile
    const int aRow = wM * 64 + (lane & 15);
    const int aC   = lane >> 4;
    const int bRow = wN * 64 + (lane & 7) + ((lane >> 4) & 1) * 8;
    const int bC   = (lane >> 3) & 1;

    float c[4][8][4];
#pragma unroll
    for (int tm = 0; tm < 4; tm++)
#pragma unroll
        for (int tn = 0; tn < 8; tn++)
#pragma unroll
            for (int i = 0; i < 4; i++) c[tm][tn][i] = 0.f;

    load_stage(0, 0); cp_commit();
    load_stage(1, 1); cp_commit();

#pragma unroll 1
    for (int it = 0; it < 16; it++) {
        cp_wait1();
        __syncthreads();
        const int s = it - (it / 3) * 3;
        const unsigned sa = smbase + s * HG_STG;
        const unsigned sbB = sa + 16384;

#pragma unroll
        for (int k16 = 0; k16 < 4; k16++) {
            unsigned a[4][4], b[4][4];
#pragma unroll
            for (int tm = 0; tm < 4; tm++)
                ldsm4(a[tm][0], a[tm][1], a[tm][2], a[tm][3],
                      sa + off16(aRow + tm * 16, k16 * 2 + aC));
#pragma unroll
            for (int p = 0; p < 4; p++)
                ldsm4(b[p][0], b[p][1], b[p][2], b[p][3],
                      sbB + off16(bRow + p * 16, k16 * 2 + bC));
#pragma unroll
            for (int tm = 0; tm < 4; tm++)
#pragma unroll
                for (int tn = 0; tn < 8; tn++)
                    mma_f16(c[tm][tn], a[tm], &b[tn >> 1][(tn & 1) * 2]);
            if (k16 == 0 && it + 2 < 16) load_stage((it + 2) % 3, it + 2);
        }
        cp_commit();
    }

    const int grp = lane >> 2, qd = lane & 3;
    __syncthreads();

    if (EPI == 0) {
        const int which = n0 >> 10;
        __half* dst = (which == 0) ? g_qh : ((which == 1) ? g_kh : g_vh);
        const float sc = (which == 0) ? QSCALE : 1.0f;
        __half* st = gsm;
#pragma unroll
        for (int tm = 0; tm < 4; tm++)
#pragma unroll
            for (int hf = 0; hf < 2; hf++) {
                const int row = wM * 64 + tm * 16 + grp + hf * 8;
#pragma unroll
                for (int tn = 0; tn < 8; tn++) {
                    const int col = wN * 64 + tn * 8 + qd * 2;
                    __half2 hv = __floats2half2_rn(c[tm][tn][hf * 2 + 0] * sc,
                                                   c[tm][tn][hf * 2 + 1] * sc);
                    *(__half2*)(st + row * 136 + col) = hv;
                }
            }
        __syncthreads();
        const int r = tid;
        const int mrow = m0 + r;
        if (mrow < Mv) {
            const int b_ = mrow / NTOK;
            const int n_ = mrow - b_ * NTOK;
#pragma unroll
            for (int seg = 0; seg < 2; seg++) {
                const int gcol = n0 + seg * 64;
                const int h = (gcol & 1023) >> 6;
                __half* base = dst + ((size_t)(b_ * Hn + h) * NTOK + n_) * DHn;
                const __half* src = st + r * 136 + seg * 64;
#pragma unroll
                for (int i = 0; i < 8; i++)
                    *(uint4*)(base + i * 8) = *(const uint4*)(src + i * 8);
            }
        }
    } else {
        float* st = (float*)gsm;
#pragma unroll
        for (int tm = 0; tm < 4; tm++)
#pragma unroll
            for (int hf = 0; hf < 2; hf++) {
                const int row = wM * 64 + tm * 16 + grp + hf * 8;
#pragma unroll
                for (int tn = 0; tn < 8; tn++) {
                    const int col = wN * 64 + tn * 8 + qd * 2;
                    float2 v = make_float2(c[tm][tn][hf * 2 + 0],
                                           c[tm][tn][hf * 2 + 1]);
                    *(float2*)(st + row * 136 + col) = v;
                }
            }
        __syncthreads();
        const int r = tid;
        const int mrow = m0 + r;
        if (mrow < Mv) {
            const float* src = st + r * 136;
            const float* bsrc = bias + n0;
            float* dstp = out + (size_t)mrow * DIMn + n0;
#pragma unroll
            for (int i = 0; i < 32; i++) {
                float4 v = *(const float4*)(src + i * 4);
                float4 bb = *(const float4*)(bsrc + i * 4);
                v.x += bb.x; v.y += bb.y; v.z += bb.z; v.w += bb.w;
                *(float4*)(dstp + i * 4) = v;
            }
        }
    }
}

// ---------------------------------------------------------------------------
// cvt v2 (R14; PROTECTED)
// ---------------------------------------------------------------------------
#define CVT_XBLK  MQKV
#define CVT_WBLK  (4 * DIMn * DIMn / 1024)
#define CVT_BLKS  (CVT_XBLK + CVT_WBLK)
#define WQ_ELEMS  (3 * DIMn * DIMn)

__global__ __launch_bounds__(256) void cvt_all_kernel(
    const float* __restrict__ x, const float* __restrict__ wqkv,
    const float* __restrict__ wout)
{
    const int tid = threadIdx.x;
    if (blockIdx.x < CVT_XBLK) {
        const int row = blockIdx.x;
        const int b = row / NTOK;
        const int n = row - b * NTOK;
        const int col = tid * 4;
        float4 v = make_float4(0.f, 0.f, 0.f, 0.f);
        if (n < NREAL)
            v = *(const float4*)(x + ((size_t)b * NREAL + n) * DIMn + col);
        uint2 u;
        u.x = packh2(v.x, v.y);
        u.y = packh2(v.z, v.w);
        *(uint2*)(g_xh + (size_t)row * DIMn + col) = u;
    } else {
        const size_t e = ((size_t)(blockIdx.x - CVT_XBLK) * 256 + tid) * 4;
        float4 v;
        __half* dst;
        size_t o;
        if (e < WQ_ELEMS) {
            v = *(const float4*)(wqkv + e);
            dst = g_wqkvh; o = e;
        } else {
            o = e - WQ_ELEMS;
            v = *(const float4*)(wout + o);
            dst = g_wouth;
        }
        uint2 u;
        u.x = packh2(v.x, v.y);
        u.y = packh2(v.z, v.w);
        *(uint2*)(dst + o) = u;
    }
}

// ---------------------------------------------------------------------------
// FlashAttention-2-style fused attention: register-resident online softmax.
// 128-thread blocks, 64 queries; phases load K+V of one tile together
// (16KB) into a 2-buffer ring. No S smem, no softmax barrier.
// smem: Q[64][64] @0 (8K), phase bufs 2 x 16K @8192. Total 40960 -> 4 CTAs/SM.
// bx 0..15 image row-pairs (5 phases), bx 16..19 text tiles (LPT order).
// ---------------------------------------------------------------------------
#define ATT_QOFF 0
#define ATT_BUF0 8192
#define ATT_SMEM 40960

__device__ __forceinline__ void att_cp_tile(unsigned dstbase, const __half* g,
                                            int tid) {
#pragma unroll
    for (int r = 0; r < 4; r++) {
        int id = tid + 128 * r;
        int row = id >> 3, c = id & 7;
        cp16(dstbase + off16(row, c), g + row * 64 + c * 8, true);
    }
}

__global__ __launch_bounds__(128, 4) void attn_fused_kernel()
{
    extern __shared__ char sm[];
    const unsigned sb = (unsigned)__cvta_generic_to_shared(sm);

    const int bh = blockIdx.y;
    const int bx = blockIdx.x;
    const bool isText = (bx >= 16);      // LPT: image blocks first
    const int tid = threadIdx.x, lane = tid & 31, warp = tid >> 5;
    const int grp = lane >> 2, qd = lane & 3;

    const int tIdx = bx - 16;
    const int qtok0 = isText ? tIdx * 64 : TXT + bx * 64;

    const __half* qg = g_qh + (size_t)bh * HD + (size_t)qtok0 * DHn;
    const __half* kg = g_kh + (size_t)bh * HD;
    const __half* vg = g_vh + (size_t)bh * HD;

    const int nK = isText ? (tIdx + 1) : 5;

    auto load_phase = [&](int ph) {
        const unsigned d = sb + ATT_BUF0 + (unsigned)(ph & 1) * 16384;
        const __half* ks;
        const __half* vs;
        if (isText || ph < 4) {
            ks = kg + (size_t)ph * 64 * DHn;
            vs = vg + (size_t)ph * 64 * DHn;
        } else {
            ks = kg + (size_t)qtok0 * DHn;
            vs = vg + (size_t)qtok0 * DHn;
        }
        att_cp_tile(d, ks, tid);
        att_cp_tile(d + 8192, vs, tid);
    };

    // prologue: Q + phase0 (group 0), phase1 (group 1)
    att_cp_tile(sb + ATT_QOFF, qg, tid);
    load_phase(0);
    cp_commit();
    if (nK > 1) load_phase(1);
    cp_commit();

    const int aRow = warp * 16 + (lane & 15);
    const int aC   = lane >> 4;
    const int bRow = (lane & 7) + ((lane >> 4) & 1) * 8;
    const int bC   = (lane >> 3) & 1;
    const int kb   = (warp >> 1) * 32;   // img: per-warp key base in own tile

    // online softmax state (rows warp*16+grp and +8)
    float co[8][4];
#pragma unroll
    for (int tn = 0; tn < 8; tn++)
#pragma unroll
        for (int i = 0; i < 4; i++) co[tn][i] = 0.f;
    float m0 = -FLT_MAX, m1 = -FLT_MAX, l0 = 0.f, l1 = 0.f;

#pragma unroll 1
    for (int ph = 0; ph < nK; ph++) {
        cp_wait1();
        __syncthreads();
        const unsigned kvb = sb + ATT_BUF0 + (unsigned)(ph & 1) * 16384;
        const unsigned vbb = kvb + 8192;
        const bool imgTile = (!isText) && (ph == 4);
        const int nT = imgTile ? 4 : 8;      // score n8-tiles this phase

        // ---- QK scores into registers ----
        float cs[8][4];
#pragma unroll
        for (int tn = 0; tn < 8; tn++)
#pragma unroll
            for (int i = 0; i < 4; i++) cs[tn][i] = 0.f;
#pragma unroll
        for (int k16 = 0; k16 < 4; k16++) {
            unsigned a[4], b[4][4];
            ldsm4(a[0], a[1], a[2], a[3],
                  sb + ATT_QOFF + off16(aRow, k16 * 2 + aC));
            if (!imgTile) {
#pragma unroll
                for (int p = 0; p < 4; p++)
                    ldsm4(b[p][0], b[p][1], b[p][2], b[p][3],
                          kvb + off16(p * 16 + bRow, k16 * 2 + bC));
#pragma unroll
                for (int tn = 0; tn < 8; tn++)
                    mma_f16(cs[tn], a, &b[tn >> 1][(tn & 1) * 2]);
            } else {
#pragma unroll
                for (int p = 0; p < 2; p++)
                    ldsm4(b[p][0], b[p][1], b[p][2], b[p][3],
                          kvb + off16(kb + p * 16 + bRow, k16 * 2 + bC));
#pragma unroll
                for (int tn = 0; tn < 4; tn++)
                    mma_f16(cs[tn], a, &b[tn >> 1][(tn & 1) * 2]);
            }
        }

        // ---- masks (in registers) ----
        if (isText && ph == nK - 1) {
            const int j0 = ph * 64;
            const int row0 = qtok0 + warp * 16 + grp;
#pragma unroll
            for (int tn = 0; tn < 8; tn++) {
                const int col = j0 + tn * 8 + qd * 2;
                if (col > row0)         cs[tn][0] = -1e30f;
                if (col + 1 > row0)     cs[tn][1] = -1e30f;
                if (col > row0 + 8)     cs[tn][2] = -1e30f;
                if (col + 1 > row0 + 8) cs[tn][3] = -1e30f;
            }
        }
        if (imgTile) {
            const int q0l = (warp * 16 + grp) & 31;
#pragma unroll
            for (int tn = 0; tn < 4; tn++) {
                const int j = tn * 8 + qd * 2;
                if (j > q0l)         cs[tn][0] = -1e30f;
                if (j + 1 > q0l)     cs[tn][1] = -1e30f;
                if (j > q0l + 8)     cs[tn][2] = -1e30f;
                if (j + 1 > q0l + 8) cs[tn][3] = -1e30f;
            }
        }

        // ---- online softmax update ----
        float mx0 = -FLT_MAX, mx1 = -FLT_MAX;
#pragma unroll
        for (int tn = 0; tn < 8; tn++) {
            if (tn >= nT) break;
            mx0 = fmaxf(mx0, fmaxf(cs[tn][0], cs[tn][1]));
            mx1 = fmaxf(mx1, fmaxf(cs[tn][2], cs[tn][3]));
        }
        mx0 = fmaxf(mx0, __shfl_xor_sync(0xffffffffu, mx0, 1));
        mx0 = fmaxf(mx0, __shfl_xor_sync(0xffffffffu, mx0, 2));
        mx1 = fmaxf(mx1, __shfl_xor_sync(0xffffffffu, mx1, 1));
        mx1 = fmaxf(mx1, __shfl_xor_sync(0xffffffffu, mx1, 2));

        const float nm0 = fmaxf(m0, mx0);
        const float nm1 = fmaxf(m1, mx1);
        const float sc0 = __expf(m0 - nm0);
        const float sc1 = __expf(m1 - nm1);
        m0 = nm0; m1 = nm1;
        l0 *= sc0; l1 *= sc1;
#pragma unroll
        for (int tn = 0; tn < 8; tn++) {
            co[tn][0] *= sc0; co[tn][1] *= sc0;
            co[tn][2] *= sc1; co[tn][3] *= sc1;
        }

        // exp + pack P fragments
        unsigned ph2[8][2];
#pragma unroll
        for (int tn = 0; tn < 8; tn++) {
            if (tn >= nT) { ph2[tn][0] = 0; ph2[tn][1] = 0; continue; }
            const float p0 = __expf(cs[tn][0] - m0);
            const float p1 = __expf(cs[tn][1] - m0);
            const float p2 = __expf(cs[tn][2] - m1);
            const float p3 = __expf(cs[tn][3] - m1);
            l0 += p0 + p1;
            l1 += p2 + p3;
            ph2[tn][0] = packh2(p0, p1);
            ph2[tn][1] = packh2(p2, p3);
        }

        // ---- AV: P (regs) x V (smem) ----
        const int nk16 = imgTile ? 2 : 4;
#pragma unroll
        for (int k16 = 0; k16 < 4; k16++) {
            if (k16 >= nk16) break;
            unsigned pa[4];
            pa[0] = ph2[2 * k16][0];
            pa[1] = ph2[2 * k16][1];
            pa[2] = ph2[2 * k16 + 1][0];
            pa[3] = ph2[2 * k16 + 1][1];
            unsigned vb[4][4];
            const int vrow = (imgTile ? kb : 0) + k16 * 16 + (lane & 15);
#pragma unroll
            for (int n16 = 0; n16 < 4; n16++)
                ldsm4t(vb[n16][0], vb[n16][1], vb[n16][2], vb[n16][3],
                       vbb + off16(vrow, n16 * 2 + (lane >> 4)));
#pragma unroll
            for (int tn = 0; tn < 8; tn++)
                mma_f16(co[tn], pa, &vb[tn >> 1][(tn & 1) * 2]);
        }

        __syncthreads();
        if (ph + 2 < nK) load_phase(ph + 2);
        cp_commit();
    }

    // ---- finalize: reduce l across quad, normalize, stage, store ----
    l0 += __shfl_xor_sync(0xffffffffu, l0, 1);
    l0 += __shfl_xor_sync(0xffffffffu, l0, 2);
    l1 += __shfl_xor_sync(0xffffffffu, l1, 1);
    l1 += __shfl_xor_sync(0xffffffffu, l1, 2);
    const float inv0 = 1.f / l0;
    const float inv1 = 1.f / l1;

    __syncthreads();                       // phase buffers free for staging
    __half* st = (__half*)(sm + ATT_BUF0); // 64 x 72 halfs (9216 B)
#pragma unroll
    for (int tn = 0; tn < 8; tn++) {
        const int col = tn * 8 + qd * 2;
        *(__half2*)(st + (warp * 16 + grp) * 72 + col) =
            __floats2half2_rn(co[tn][0] * inv0, co[tn][1] * inv0);
        *(__half2*)(st + (warp * 16 + grp + 8) * 72 + col) =
            __floats2half2_rn(co[tn][2] * inv1, co[tn][3] * inv1);
    }
    __syncthreads();
    {
        const int row = tid >> 1, seg = tid & 1;
        const int token = qtok0 + row;
        if (token < NREAL) {
            const int b_ = bh >> 4, h_ = bh & 15;
            const int m = b_ * NREAL + token;
            __half* dstp = g_oh + (size_t)m * DIMn + h_ * 64 + seg * 32;
            const __half* srcp = st + row * 72 + seg * 32;
#pragma unroll
            for (int i = 0; i < 4; i++)
                *(uint4*)(dstp + i * 8) = *(const uint4*)(srcp + i * 8);
        }
    }
}

// ---------------------------------------------------------------------------
// Launch
// ---------------------------------------------------------------------------
extern "C" void kernel_launch(void* const* d_in, const int* in_sizes, int n_in,
                              void* d_out, int out_size)
{
    (void)in_sizes; (void)n_in; (void)out_size;
    const float* x     = (const float*)d_in[0];
    const float* w_qkv = (const float*)d_in[1];
    const float* w_out = (const float*)d_in[2];
    const float* b_out = (const float*)d_in[3];
    float* out = (float*)d_out;

    cudaFuncSetAttribute(attn_fused_kernel,
                         cudaFuncAttributeMaxDynamicSharedMemorySize, ATT_SMEM);
    cudaFuncSetAttribute(hgemm_kernel<0>,
                         cudaFuncAttributeMaxDynamicSharedMemorySize, HG_SMEM);
    cudaFuncSetAttribute(hgemm_kernel<1>,
                         cudaFuncAttributeMaxDynamicSharedMemorySize, HG_SMEM);

    void* p_xh;    cudaGetSymbolAddress(&p_xh, g_xh);
    void* p_wqkv;  cudaGetSymbolAddress(&p_wqkv, g_wqkvh);
    void* p_wout;  cudaGetSymbolAddress(&p_wout, g_wouth);
    void* p_oh;    cudaGetSymbolAddress(&p_oh, g_oh);

    // 0) fp32 -> fp16 conversions
    cvt_all_kernel<<<CVT_BLKS, 256>>>(x, w_qkv, w_out);

    // 1) QKV projection (fp16 tensor cores)
    hgemm_kernel<0><<<dim3(24, 160), 128, HG_SMEM>>>(
        (const __half*)p_xh, (const __half*)p_wqkv, nullptr, nullptr, MQKV);

    // 2) fused attention (FA2-style register softmax, LPT order)
    attn_fused_kernel<<<dim3(20, 256), 128, ATT_SMEM>>>();

    // 3) output projection + bias
    hgemm_kernel<1><<<dim3(8, 160), 128, HG_SMEM>>>(
        (const __half*)p_oh, (const __half*)p_wout, b_out, out, MOUT);
}